// round 14
// baseline (speedup 1.0000x reference)
#include <cuda_runtime.h>
#include <cuda_bf16.h>
#include <math.h>
#include <stdint.h>

#define BB 256
#define TT 128
#define DD 64
#define HH 512
#define AA 128
#define OO 32
#define NBLK 128
#define NTHR 512

__device__ uint32_t g_KbT[BB * 64 * TT];      // K transposed: [(b*64+j)*128 + t], bf16x2 over a
__device__ float g_V[BB * TT * AA];
__device__ uint32_t g_WBLo[16 * 96 * 256];    // stage lo residual [hg][n][kq]
__device__ uint32_t g_WKVHi[NBLK * 16 * 256];
__device__ uint32_t g_WKVLo[NBLK * 16 * 256];
__device__ uint32_t g_WBaseHi[NBLK * 64 * 96];
__device__ uint32_t g_WBaseLo[NBLK * 64 * 96];
__device__ float g_ctx[BB * AA];
__device__ float g_h[BB * HH];
__device__ uint32_t g_hHi[BB * 256];
__device__ uint32_t g_hLo[BB * 256];
__device__ uint32_t g_dA[BB * 256];
__device__ uint32_t g_dB[BB * 256];
__device__ unsigned g_cnt[8 * 32];
__device__ unsigned g_gen[8 * 32];

__device__ __forceinline__ float softplusf(float x) {
    return (x > 20.f) ? x : log1pf(expf(x));
}
__device__ __forceinline__ float sigmoidf(float x) {
    return 1.f / (1.f + expf(-x));
}
__device__ __forceinline__ float bfr(float x) {
    return __bfloat162float(__float2bfloat16(x));
}
__device__ __forceinline__ void mma16(float* d, const uint32_t* a, const uint32_t* b) {
    asm volatile(
        "mma.sync.aligned.m16n8k16.row.col.f32.bf16.bf16.f32 "
        "{%0,%1,%2,%3},{%4,%5,%6,%7},{%8,%9},{%0,%1,%2,%3};"
        : "+f"(d[0]), "+f"(d[1]), "+f"(d[2]), "+f"(d[3])
        : "r"(a[0]), "r"(a[1]), "r"(a[2]), "r"(a[3]), "r"(b[0]), "r"(b[1]));
}
__device__ __forceinline__ uint32_t pack_bf2(float a, float b) {
    __nv_bfloat162 t = __floats2bfloat162_rn(a, b);
    return *(uint32_t*)&t;
}
__device__ __forceinline__ uint32_t s2u(const void* p) {
    return (uint32_t)__cvta_generic_to_shared(p);
}
__device__ __forceinline__ void ldsm4(uint32_t* r, uint32_t a) {
    asm volatile("ldmatrix.sync.aligned.m8n8.x4.shared.b16 {%0,%1,%2,%3}, [%4];"
                 : "=r"(r[0]), "=r"(r[1]), "=r"(r[2]), "=r"(r[3]) : "r"(a));
}
__device__ __forceinline__ void ldsm2(uint32_t* r, uint32_t a) {
    asm volatile("ldmatrix.sync.aligned.m8n8.x2.shared.b16 {%0,%1}, [%2];"
                 : "=r"(r[0]), "=r"(r[1]) : "r"(a));
}

// software fallback barrier (atomic, padded counters)
__device__ __forceinline__ void gbar_sw(int idx) {
    __syncthreads();
    if (threadIdx.x == 0) {
        unsigned* cntp = &g_cnt[idx * 32];
        unsigned* genp = &g_gen[idx * 32];
        unsigned gen;
        asm volatile("ld.acquire.gpu.global.u32 %0, [%1];" : "=r"(gen) : "l"(genp));
        unsigned old;
        asm volatile("atom.release.gpu.global.add.u32 %0, [%1], %2;"
                     : "=r"(old) : "l"(cntp), "r"(1u));
        if (old == 15u) {
            asm volatile("st.relaxed.gpu.global.u32 [%0], %1;" :: "l"(cntp), "r"(0u));
            asm volatile("st.release.gpu.global.u32 [%0], %1;" :: "l"(genp), "r"(gen + 1u));
        } else {
            unsigned cur = gen;
            while (cur == gen) {
                __nanosleep(32);
                asm volatile("ld.acquire.gpu.global.u32 %0, [%1];" : "=r"(cur) : "l"(genp));
            }
        }
    }
    __syncthreads();
}

// hardware cluster barrier (group == 16-CTA cluster)
__device__ __forceinline__ void cbar() {
    asm volatile("barrier.cluster.arrive.aligned;" ::: "memory");
    asm volatile("barrier.cluster.wait.aligned;" ::: "memory");
}

#define GBAR() do { if (useClu) cbar(); else gbar_sw(gid); } while (0)

#define O_W  0
#define O_A  99840
#define O_AL 133120
#define O_Z  166400
#define O_SB 190976
#define O_SZ 199168
#define O_PB 211456
#define SMEM_BYTES 224256

__global__ void __launch_bounds__(NTHR, 1) mega(
    const float* __restrict__ x_states, const float* __restrict__ x_dts,
    const float* __restrict__ Wq, const float* __restrict__ bq,
    const float* __restrict__ Wk, const float* __restrict__ bk,
    const float* __restrict__ Wv, const float* __restrict__ bv,
    const float* __restrict__ W_gd, const float* __restrict__ b_gd,
    const float* __restrict__ W_tau, const float* __restrict__ b_tau,
    const float* __restrict__ gleak, const float* __restrict__ cm,
    const float* __restrict__ W_fc, const float* __restrict__ b_fc,
    float* __restrict__ out, int useClu)
{
    extern __shared__ char smraw[];
    __shared__ float sleak[32], sbtau[32];
    uint32_t* Ws   = (uint32_t*)(smraw + O_W);
    uint32_t* AsHi = (uint32_t*)(smraw + O_A);
    uint32_t* AsLo = (uint32_t*)(smraw + O_AL);
    float (*zz)[96]    = (float(*)[96])(smraw + O_Z);
    float (*sbase)[64] = (float(*)[64])(smraw + O_SB);
    float (*sz0)[96]   = (float(*)[96])(smraw + O_SZ);
    uint32_t uW  = s2u(smraw + O_W);
    uint32_t uA  = s2u(smraw + O_A);
    uint32_t uAL = s2u(smraw + O_AL);
    uint32_t uZ  = s2u(smraw + O_Z);
    uint32_t uSB = s2u(smraw + O_SB);
    uint32_t uPB = s2u(smraw + O_PB);

    int bid = blockIdx.x, tid = threadIdx.x;
    int lane = tid & 31, wid = tid >> 5;
    int gid = bid >> 4, hg = bid & 15;
    int m0 = gid * 32, h0 = hg * 32;

    // ===== prep =====
    if (tid < 32) {
        sleak[tid] = softplusf(cm[h0 + tid]) + softplusf(gleak[h0 + tid]);
        sbtau[tid] = b_tau[h0 + tid];
    }
    for (int idx = tid; idx < 96 * 256; idx += NTHR) {
        int n = idx >> 8, kq = idx & 255, k0 = kq * 2;
        float w0, w1;
        if (n < 32)      { w0 = W_gd[(64 + k0) * 1024 + h0 + n];       w1 = W_gd[(65 + k0) * 1024 + h0 + n]; }
        else if (n < 64) { w0 = W_gd[(64 + k0) * 1024 + 512 + h0 + n - 32]; w1 = W_gd[(65 + k0) * 1024 + 512 + h0 + n - 32]; }
        else             { w0 = W_tau[k0 * 512 + h0 + n - 64];         w1 = W_tau[(k0 + 1) * 512 + h0 + n - 64]; }
        float a = bfr(w0), b = bfr(w1);
        Ws[n * 260 + kq] = pack_bf2(a, b);
        g_WBLo[(hg * 96 + n) * 256 + kq] = pack_bf2(w0 - a, w1 - b);
    }
    for (int idx = tid; idx < 16 * 256; idx += NTHR) {
        int n = idx >> 8, kq = idx & 255, k0 = kq * 2;
        int nn = hg * 16 + n, ncol = nn & 127;
        const float* W = (nn < 128) ? Wk : Wv;
        float w0 = W[k0 * 128 + ncol], w1 = W[(k0 + 1) * 128 + ncol];
        float a = bfr(w0), b = bfr(w1);
        g_WKVHi[(bid * 16 + n) * 256 + kq] = pack_bf2(a, b);
        g_WKVLo[(bid * 16 + n) * 256 + kq] = pack_bf2(w0 - a, w1 - b);
    }
    for (int idx = tid; idx < 64 * 96; idx += NTHR) {
        int n = idx / 96, kq = idx - n * 96, k0 = kq * 2;
        int row0 = (k0 < 64) ? k0 : (k0 + 512);
        int col = (n < 32) ? (h0 + n) : (512 + h0 + n - 32);
        float w0 = W_gd[row0 * 1024 + col], w1 = W_gd[(row0 + 1) * 1024 + col];
        float a = bfr(w0), b = bfr(w1);
        g_WBaseHi[(bid * 64 + n) * 96 + kq] = pack_bf2(a, b);
        g_WBaseLo[(bid * 64 + n) * 96 + kq] = pack_bf2(w0 - a, w1 - b);
    }
    for (int idx = tid; idx < 32 * HH; idx += NTHR) g_h[m0 * HH + idx] = 0.f;
    {
        int mzr = tid >> 4, czc = tid & 15;
        g_hHi[(m0 + mzr) * 256 + hg * 16 + czc] = 0;
        g_hLo[(m0 + mzr) * 256 + hg * 16 + czc] = 0;
    }
    GBAR();

    float hreg[2] = {0.f, 0.f}, rk1[2], rk2[2], rk3[2], dd[2];
    int kh = wid >> 3, wl = wid & 7;
    int wm = (wl >> 2) * 16, wn = (wl & 3) * 24;
    int qa = lane & 3;
    int aSel = (lane >> 4) << 2;
    int bSel = ((lane >> 3) & 1) << 2;
    int rowA_st = (wm + (lane & 15)) * 260 + aSel;
    int rowB0 = (wn + 0 * 8 + (lane & 7)) * 260 + bSel;
    int rowB1 = (wn + 1 * 8 + (lane & 7)) * 260 + bSel;
    int rowB2 = (wn + 2 * 8 + (lane & 7)) * 260 + bSel;
    long loN0 = (long)(hg * 96 + wn + 0 * 8 + (lane >> 2)) * 256 + qa;
    long loN1 = (long)(hg * 96 + wn + 1 * 8 + (lane >> 2)) * 256 + qa;
    long loN2 = (long)(hg * 96 + wn + 2 * 8 + (lane >> 2)) * 256 + qa;
    int wkn = wid & 1, wkm = (wid >> 1) & 1, wks = wid >> 2;
    int rowA_kv = (wkm * 16 + (lane & 15)) * 260 + aSel;
    int rowB_kv = (wkn * 8 + (lane & 7)) * 260 + bSel;
    int wbk2 = wid >> 3, wbm2 = (wid >> 2) & 1, wbn2 = wid & 3;
    int rowA_bs = (wbm2 * 16 + (lane & 15)) * 100 + aSel;

    for (int t = 0; t < TT; t++) {
        // ---- KV (tensorized): row t-1; A(h) preserved into stage0 ----
        if (t > 0) {
#pragma unroll
            for (int i = 0; i < 4; i++) {
                int u4 = i * 512 + tid;
                int m = u4 >> 6, q4 = u4 & 63;
                *(uint4*)&AsHi[m * 260 + q4 * 4] = ((const uint4*)&g_hHi[(m0 + m) * 256])[q4];
                *(uint4*)&AsLo[m * 260 + q4 * 4] = ((const uint4*)&g_hLo[(m0 + m) * 256])[q4];
            }
            uint32_t* Bh = (uint32_t*)(smraw + O_Z);
            uint32_t* Bl = (uint32_t*)(smraw + O_SB);
#pragma unroll
            for (int i = 0; i < 2; i++) {
                int u4 = i * 512 + tid;
                int n = u4 >> 6, q4 = u4 & 63;
                *(uint4*)&Bh[n * 260 + q4 * 4] = ((const uint4*)&g_WKVHi[(bid * 16 + n) * 256])[q4];
                *(uint4*)&Bl[n * 260 + q4 * 4] = ((const uint4*)&g_WKVLo[(bid * 16 + n) * 256])[q4];
            }
            __syncthreads();
            float acc[4] = {0.f, 0.f, 0.f, 0.f};
#pragma unroll
            for (int it = 0; it < 8; it++) {
                int kq0 = wks * 64 + it * 8;
                uint32_t ahi[4], alo[4], bhi[2], blo[2];
                ldsm4(ahi, uA  + (rowA_kv + kq0) * 4);
                ldsm4(alo, uAL + (rowA_kv + kq0) * 4);
                ldsm2(bhi, uZ  + (rowB_kv + kq0) * 4);
                ldsm2(blo, uSB + (rowB_kv + kq0) * 4);
                mma16(acc, ahi, bhi);
                mma16(acc, alo, bhi);
                mma16(acc, ahi, blo);
            }
            __syncthreads();
            float* pkv = (float*)(smraw + O_SZ);
            {
                int ml = wkm * 16 + (lane >> 2), nl = wkn * 8 + (lane & 3) * 2;
                int off = wks * 512 + ml * 16 + nl;
                pkv[off] = acc[0]; pkv[off + 1] = acc[1];
                pkv[off + 128] = acc[2]; pkv[off + 129] = acc[3];
            }
            __syncthreads();
            {
                int m = tid >> 4, n = tid & 15;
                float s = pkv[m * 16 + n] + pkv[512 + m * 16 + n] +
                          pkv[1024 + m * 16 + n] + pkv[1536 + m * 16 + n];
                if (hg < 8) {
                    int ncol = hg * 16 + n;
                    s += bk[ncol];
                    float os = __shfl_xor_sync(~0u, s, 1);
                    if (!(tid & 1))
                        g_KbT[((m0 + m) * 64 + (ncol >> 1)) * TT + (t - 1)] = pack_bf2(s, os);
                } else {
                    int ncol = (hg - 8) * 16 + n;
                    s += bv[ncol];
                    g_V[((m0 + m) * TT + (t - 1)) * AA + ncol] = s;
                }
            }
            GBAR();
        }

        // ---- ATTN: scratch in O_SZ (keeps AsHi/AsLo intact) ----
        {
            float* aq   = (float*)(smraw + O_SZ);
            float* asc  = aq + 256;
            float* actx = asc + 256;
            float* axs  = actx + 512;
            float* ared = axs + 128;
            int hB = tid >> 8, lt = tid & 255;
            int b = bid * 2 + hB;
            if (t == 0) {
                if (lt < 128) g_ctx[b * AA + lt] = 0.f;
            } else {
                if (lt < DD) axs[hB * 64 + lt] = x_states[(b * TT + t) * DD + lt];
                __syncthreads();
                if (lt < 128) {
                    float qv = bq[lt];
#pragma unroll 16
                    for (int d = 0; d < DD; d++) qv += axs[hB * 64 + d] * Wq[d * AA + lt];
                    aq[hB * 128 + lt] = qv;
                }
                __syncthreads();
                float s = -1e30f;
                if (lt < t) {
                    const uint32_t* Kp = &g_KbT[b * 64 * TT + lt];
                    const float* qh = &aq[hB * 128];
                    float dot = 0.f;
#pragma unroll 8
                    for (int j = 0; j < 64; j++) {
                        uint32_t kv = Kp[j * TT];
                        float2 f = __bfloat1622float2(*(__nv_bfloat162*)&kv);
                        dot += f.x * qh[2 * j] + f.y * qh[2 * j + 1];
                    }
                    s = dot * (1.f / 11.313708498984761f);
                }
                float m = s;
#pragma unroll
                for (int o = 16; o > 0; o >>= 1) m = fmaxf(m, __shfl_xor_sync(~0u, m, o));
                if (lane == 0) ared[hB * 8 + (wid & 7)] = m;
                __syncthreads();
                m = ared[hB * 8];
#pragma unroll
                for (int i = 1; i < 8; i++) m = fmaxf(m, ared[hB * 8 + i]);
                float e = (lt < t) ? expf(s - m) : 0.f;
                float su = e;
#pragma unroll
                for (int o = 16; o > 0; o >>= 1) su += __shfl_xor_sync(~0u, su, o);
                __syncthreads();
                if (lane == 0) ared[hB * 8 + (wid & 7)] = su;
                __syncthreads();
                su = 0.f;
#pragma unroll
                for (int i = 0; i < 8; i++) su += ared[hB * 8 + i];
                if (lt < 128) asc[hB * 128 + lt] = (lt < t) ? (e / su) : 0.f;
                __syncthreads();
                {
                    int a = lt & 127, th = lt >> 7;
                    int tlim = (t + 7) & ~7;
                    float c = 0.f;
#pragma unroll 8
                    for (int sx = th; sx < tlim; sx += 2)
                        c += asc[hB * 128 + sx] * g_V[(b * TT + sx) * AA + a];
                    actx[(hB * 2 + th) * 128 + a] = c;
                }
                __syncthreads();
                if (lt < 128)
                    g_ctx[b * AA + lt] = actx[hB * 256 + lt] + actx[hB * 256 + 128 + lt];
            }
            GBAR();
        }

        // ---- 4 RK stages ----
        for (int stage = 0; stage < 4; stage++) {
            float acc[3][4];
#pragma unroll
            for (int s = 0; s < 3; s++)
#pragma unroll
                for (int i = 0; i < 4; i++) acc[s][i] = 0.f;

            if (stage == 0) {
                uint32_t* bAhi = (uint32_t*)(smraw + O_Z);
                uint32_t* bAlo = (uint32_t*)(smraw + O_PB);
#pragma unroll
                for (int i = 0; i < 6; i++) {
                    int idx = i * 512 + tid;
                    int m = idx / 96, kq = idx - m * 96;
                    int k0 = kq * 2;
                    float a0, a1;
                    if (kq < 32) {
                        const float* xr = &x_states[((m0 + m) * TT + t) * DD];
                        a0 = xr[k0]; a1 = xr[k0 + 1];
                    } else {
                        const float* cr = &g_ctx[(m0 + m) * AA];
                        a0 = cr[k0 - 64]; a1 = cr[k0 - 63];
                    }
                    float h0v = bfr(a0), h1v = bfr(a1);
                    bAhi[m * 100 + kq] = pack_bf2(h0v, h1v);
                    bAlo[m * 100 + kq] = pack_bf2(a0 - h0v, a1 - h1v);
                }
                __syncthreads();
                {
                    float accb[2][4];
#pragma unroll
                    for (int s = 0; s < 2; s++)
#pragma unroll
                        for (int i = 0; i < 4; i++) accb[s][i] = 0.f;
#pragma unroll
                    for (int ks = 0; ks < 6; ks++) {
                        int kq0 = wbk2 * 48 + ks * 8;
                        uint32_t ahi[4], alo[4];
                        ldsm4(ahi, uZ  + (rowA_bs + kq0) * 4);
                        ldsm4(alo, uPB + (rowA_bs + kq0) * 4);
#pragma unroll
                        for (int s = 0; s < 2; s++) {
                            int nrow = wbn2 * 16 + s * 8 + (lane >> 2);
                            long bix = (long)(bid * 64 + nrow) * 96 + kq0 + qa;
                            uint32_t bhi[2], blo[2];
                            bhi[0] = g_WBaseHi[bix]; bhi[1] = g_WBaseHi[bix + 4];
                            blo[0] = g_WBaseLo[bix]; blo[1] = g_WBaseLo[bix + 4];
                            mma16(accb[s], ahi, bhi);
                            mma16(accb[s], alo, bhi);
                            mma16(accb[s], ahi, blo);
                        }
                    }
                    __syncthreads();
                    float* pb = (float*)(smraw + O_Z);
#pragma unroll
                    for (int s = 0; s < 2; s++) {
                        int off = wbk2 * 2048 + (wbm2 * 16 + (lane >> 2)) * 64 +
                                  wbn2 * 16 + s * 8 + (lane & 3) * 2;
                        pb[off] = accb[s][0]; pb[off + 1] = accb[s][1];
                        pb[off + 512] = accb[s][2]; pb[off + 513] = accb[s][3];
                    }
                    __syncthreads();
#pragma unroll
                    for (int i = 0; i < 4; i++) {
                        int idx = i * 512 + tid;
                        int m = idx >> 6, n = idx & 63;
                        int col = (n < 32) ? (h0 + n) : (512 + h0 + n - 32);
                        sbase[m][n] = pb[m * 64 + n] + pb[2048 + m * 64 + n] + b_gd[col];
                    }
                }
                __syncthreads();
                if (t == 0) {
#pragma unroll
                    for (int i = 0; i < 4; i++) {
                        int u4 = i * 512 + tid;
                        int m = u4 >> 6, q4 = u4 & 63;
                        *(uint4*)&AsHi[m * 260 + q4 * 4] = ((const uint4*)&g_hHi[(m0 + m) * 256])[q4];
                        *(uint4*)&AsLo[m * 260 + q4 * 4] = ((const uint4*)&g_hLo[(m0 + m) * 256])[q4];
                    }
                    __syncthreads();
                }
#pragma unroll
                for (int it = 0; it < 8; it++) {
#pragma unroll
                    for (int kb2 = 0; kb2 < 16; kb2 += 8) {
                        int kq0 = kh * 128 + it * 16 + kb2;
                        uint32_t ahi[4], alo[4], bw[2], bl[2];
                        ldsm4(ahi, uA  + (rowA_st + kq0) * 4);
                        ldsm4(alo, uAL + (rowA_st + kq0) * 4);
                        ldsm2(bw, uW + (rowB0 + kq0) * 4);
                        bl[0] = g_WBLo[loN0 + kq0]; bl[1] = g_WBLo[loN0 + kq0 + 4];
                        mma16(acc[0], ahi, bw); mma16(acc[0], alo, bw); mma16(acc[0], ahi, bl);
                        ldsm2(bw, uW + (rowB1 + kq0) * 4);
                        bl[0] = g_WBLo[loN1 + kq0]; bl[1] = g_WBLo[loN1 + kq0 + 4];
                        mma16(acc[1], ahi, bw); mma16(acc[1], alo, bw); mma16(acc[1], ahi, bl);
                        ldsm2(bw, uW + (rowB2 + kq0) * 4);
                        bl[0] = g_WBLo[loN2 + kq0]; bl[1] = g_WBLo[loN2 + kq0 + 4];
                        mma16(acc[2], ahi, bw); mma16(acc[2], alo, bw); mma16(acc[2], ahi, bl);
                    }
                }
                __syncthreads();
            } else {
                const uint32_t* Dg = (stage == 2) ? g_dB : g_dA;
#pragma unroll
                for (int i = 0; i < 4; i++) {
                    int idx = i * 512 + tid;
                    int m = idx >> 6, q4 = idx & 63;
                    *(uint4*)&AsHi[m * 260 + q4 * 4] = ((const uint4*)&Dg[(m0 + m) * 256])[q4];
                }
                __syncthreads();
#pragma unroll
                for (int it = 0; it < 8; it++) {
#pragma unroll
                    for (int kb2 = 0; kb2 < 16; kb2 += 8) {
                        int kq0 = kh * 128 + it * 16 + kb2;
                        uint32_t ahi[4], bw[2];
                        ldsm4(ahi, uA + (rowA_st + kq0) * 4);
                        ldsm2(bw, uW + (rowB0 + kq0) * 4);
                        mma16(acc[0], ahi, bw);
                        ldsm2(bw, uW + (rowB1 + kq0) * 4);
                        mma16(acc[1], ahi, bw);
                        ldsm2(bw, uW + (rowB2 + kq0) * 4);
                        mma16(acc[2], ahi, bw);
                    }
                }
                __syncthreads();
            }

            {
                int rr = wm + (lane >> 2), cc = wn + (lane & 3) * 2;
#pragma unroll
                for (int s = 0; s < 3; s++) {
                    zz[kh * 32 + rr][cc + s * 8]         = acc[s][0];
                    zz[kh * 32 + rr][cc + s * 8 + 1]     = acc[s][1];
                    zz[kh * 32 + rr + 8][cc + s * 8]     = acc[s][2];
                    zz[kh * 32 + rr + 8][cc + s * 8 + 1] = acc[s][3];
                }
            }
            __syncthreads();
            if (stage == 0) {
#pragma unroll
                for (int i = 0; i < 6; i++) {
                    int idx = i * 512 + tid;
                    int bl = idx / 96, c = idx - bl * 96;
                    sz0[bl][c] = zz[bl][c] + zz[32 + bl][c];
                }
                __syncthreads();
            }

#pragma unroll
            for (int p = 0; p < 2; p++) {
                int idx = p * 512 + tid;
                int bl = idx >> 5, hh = idx & 31;
                int b = m0 + bl;
                float zg, zdn, zt;
                if (stage == 0) {
                    zg = sz0[bl][hh]; zdn = sz0[bl][32 + hh]; zt = sz0[bl][64 + hh];
                } else {
                    zg  = sz0[bl][hh]      + zz[bl][hh]      + zz[32 + bl][hh];
                    zdn = sz0[bl][32 + hh] + zz[bl][32 + hh] + zz[32 + bl][32 + hh];
                    zt  = sz0[bl][64 + hh] + zz[bl][64 + hh] + zz[32 + bl][64 + hh];
                }
                float gate = zg + sbase[bl][hh];
                float dyn  = zdn + sbase[bl][32 + hh];
                float tau  = softplusf(zt + sbtau[hh]);
                float hsv  = (stage == 0) ? hreg[p] : (hreg[p] + dd[p]);
                float kd   = (sigmoidf(gate) * tanhf(dyn) - hsv) / (tau + sleak[hh] + 1e-6f);
                float dt   = x_dts[b * TT + t];
                if (stage == 3) {
                    hreg[p] += dt * (rk1[p] + 3.f * rk2[p] + 3.f * rk3[p] + kd) * 0.125f;
                    g_h[b * HH + h0 + hh] = hreg[p];
                    float hi = bfr(hreg[p]);
                    float lo = hreg[p] - hi;
                    float ohi = __shfl_xor_sync(~0u, hi, 1);
                    float olo = __shfl_xor_sync(~0u, lo, 1);
                    if (!(tid & 1)) {
                        g_hHi[b * 256 + ((h0 + hh) >> 1)] = pack_bf2(hi, ohi);
                        g_hLo[b * 256 + ((h0 + hh) >> 1)] = pack_bf2(lo, olo);
                    }
                } else {
                    float dnew;
                    if (stage == 0)      { rk1[p] = kd; dnew = dt * kd * (1.f / 3.f); }
                    else if (stage == 1) { rk2[p] = kd; dnew = dt * (kd - rk1[p] * (1.f / 3.f)); }
                    else                 { rk3[p] = kd; dnew = dt * (rk1[p] - rk2[p] + kd); }
                    dd[p] = dnew;
                    float oth = __shfl_xor_sync(~0u, dnew, 1);
                    if (!(tid & 1)) {
                        uint32_t pk = pack_bf2(dnew, oth);
                        if (stage == 1) g_dB[b * 256 + ((h0 + hh) >> 1)] = pk;
                        else            g_dA[b * 256 + ((h0 + hh) >> 1)] = pk;
                    }
                }
            }
            GBAR();
        }
    }

    // ===== final projection =====
    {
        int b = bid * 2 + (tid >> 8);
        int lt = tid & 255;
        if (lt < OO) {
            float acc = b_fc[lt];
#pragma unroll 8
            for (int k = 0; k < HH; k++) acc += g_h[b * HH + k] * W_fc[k * OO + lt];
            out[b * OO + lt] = acc;
        }
    }
}

extern "C" void kernel_launch(void* const* d_in, const int* in_sizes, int n_in,
                              void* d_out, int out_size) {
    const float* x_states = (const float*)d_in[0];
    const float* x_dts    = (const float*)d_in[1];
    const float* Wq = (const float*)d_in[2];  const float* bq = (const float*)d_in[3];
    const float* Wk = (const float*)d_in[4];  const float* bk = (const float*)d_in[5];
    const float* Wv = (const float*)d_in[6];  const float* bv = (const float*)d_in[7];
    const float* W_gd = (const float*)d_in[8]; const float* b_gd = (const float*)d_in[9];
    const float* W_tau = (const float*)d_in[10]; const float* b_tau = (const float*)d_in[11];
    const float* gleak = (const float*)d_in[12]; const float* cm = (const float*)d_in[13];
    const float* W_fc = (const float*)d_in[14]; const float* b_fc = (const float*)d_in[15];
    float* out = (float*)d_out;

    cudaFuncSetAttribute(mega, cudaFuncAttributeMaxDynamicSharedMemorySize, SMEM_BYTES);
    cudaFuncSetAttribute(mega, cudaFuncAttributeNonPortableClusterSizeAllowed, 1);

    // Decide cluster feasibility with a pure host-side query (no trial launch).
    cudaLaunchConfig_t cfg = {};
    cfg.gridDim = dim3(NBLK, 1, 1);
    cfg.blockDim = dim3(NTHR, 1, 1);
    cfg.dynamicSmemBytes = SMEM_BYTES;
    cfg.stream = 0;
    cudaLaunchAttribute attrs[1];
    attrs[0].id = cudaLaunchAttributeClusterDimension;
    attrs[0].val.clusterDim = {16, 1, 1};
    cfg.attrs = attrs;
    cfg.numAttrs = 1;

    int maxClusters = 0;
    cudaError_t qe = cudaOccupancyMaxActiveClusters(&maxClusters, (const void*)mega, &cfg);
    bool useClu = (qe == cudaSuccess && maxClusters >= 8);
    if (!useClu) (void)cudaGetLastError();   // clear any query error

    if (useClu) {
        cudaLaunchKernelEx(&cfg, mega, x_states, x_dts, Wq, bq, Wk, bk, Wv, bv,
                           W_gd, b_gd, W_tau, b_tau, gleak, cm, W_fc, b_fc, out, 1);
    } else {
        mega<<<NBLK, NTHR, SMEM_BYTES>>>(x_states, x_dts, Wq, bq, Wk, bk, Wv, bv,
                                         W_gd, b_gd, W_tau, b_tau, gleak, cm,
                                         W_fc, b_fc, out, 0);
    }
}

// round 15
// speedup vs baseline: 1.0417x; 1.0417x over previous
#include <cuda_runtime.h>
#include <cuda_bf16.h>
#include <math.h>
#include <stdint.h>

#define BB 256
#define TT 128
#define DD 64
#define HH 512
#define AA 128
#define OO 32
#define NBLK 128
#define NTHR 512

__device__ uint32_t g_KbT[BB * 64 * TT];      // K transposed: [(b*64+j)*128 + t], bf16x2 over a
__device__ float g_V[BB * TT * AA];
__device__ float g_Q[BB * TT * AA];           // precomputed Q
__device__ uint32_t g_WBLo[16 * 96 * 256];    // stage lo residual [hg][n][kq]
__device__ uint32_t g_WKVHi[NBLK * 16 * 256];
__device__ uint32_t g_WKVLo[NBLK * 16 * 256];
__device__ uint32_t g_WBaseHi[NBLK * 64 * 96];
__device__ uint32_t g_WBaseLo[NBLK * 64 * 96];
__device__ float g_ctx[BB * AA];
__device__ float g_h[BB * HH];
__device__ uint32_t g_hHi[BB * 256];
__device__ uint32_t g_hLo[BB * 256];
__device__ uint32_t g_dA[BB * 256];
__device__ uint32_t g_dB[BB * 256];
__device__ unsigned g_cnt[8 * 32];
__device__ unsigned g_gen[8 * 32];

__device__ __forceinline__ float softplusf(float x) {
    return (x > 20.f) ? x : log1pf(expf(x));
}
__device__ __forceinline__ float sigmoidf(float x) {
    return 1.f / (1.f + expf(-x));
}
__device__ __forceinline__ float bfr(float x) {
    return __bfloat162float(__float2bfloat16(x));
}
__device__ __forceinline__ void mma16(float* d, const uint32_t* a, const uint32_t* b) {
    asm volatile(
        "mma.sync.aligned.m16n8k16.row.col.f32.bf16.bf16.f32 "
        "{%0,%1,%2,%3},{%4,%5,%6,%7},{%8,%9},{%0,%1,%2,%3};"
        : "+f"(d[0]), "+f"(d[1]), "+f"(d[2]), "+f"(d[3])
        : "r"(a[0]), "r"(a[1]), "r"(a[2]), "r"(a[3]), "r"(b[0]), "r"(b[1]));
}
__device__ __forceinline__ uint32_t pack_bf2(float a, float b) {
    __nv_bfloat162 t = __floats2bfloat162_rn(a, b);
    return *(uint32_t*)&t;
}
__device__ __forceinline__ uint32_t s2u(const void* p) {
    return (uint32_t)__cvta_generic_to_shared(p);
}
__device__ __forceinline__ void ldsm4(uint32_t* r, uint32_t a) {
    asm volatile("ldmatrix.sync.aligned.m8n8.x4.shared.b16 {%0,%1,%2,%3}, [%4];"
                 : "=r"(r[0]), "=r"(r[1]), "=r"(r[2]), "=r"(r[3]) : "r"(a));
}
__device__ __forceinline__ void ldsm2(uint32_t* r, uint32_t a) {
    asm volatile("ldmatrix.sync.aligned.m8n8.x2.shared.b16 {%0,%1}, [%2];"
                 : "=r"(r[0]), "=r"(r[1]) : "r"(a));
}

// acquire/release group barrier (16 blocks), padded counters
__device__ __forceinline__ void gbar(int idx) {
    __syncthreads();
    if (threadIdx.x == 0) {
        unsigned* cntp = &g_cnt[idx * 32];
        unsigned* genp = &g_gen[idx * 32];
        unsigned gen;
        asm volatile("ld.acquire.gpu.global.u32 %0, [%1];" : "=r"(gen) : "l"(genp));
        unsigned old;
        asm volatile("atom.release.gpu.global.add.u32 %0, [%1], %2;"
                     : "=r"(old) : "l"(cntp), "r"(1u));
        if (old == 15u) {
            asm volatile("st.relaxed.gpu.global.u32 [%0], %1;" :: "l"(cntp), "r"(0u));
            asm volatile("st.release.gpu.global.u32 [%0], %1;" :: "l"(genp), "r"(gen + 1u));
        } else {
            unsigned cur = gen;
            while (cur == gen) {
                __nanosleep(32);
                asm volatile("ld.acquire.gpu.global.u32 %0, [%1];" : "=r"(cur) : "l"(genp));
            }
        }
    }
    __syncthreads();
}

#define O_W  0
#define O_A  99840
#define O_AL 133120
#define O_Z  166400
#define O_SB 190976
#define O_SZ 199168
#define O_PB 211456
#define SMEM_BYTES 224256

__global__ void __launch_bounds__(NTHR, 1) mega(
    const float* __restrict__ x_states, const float* __restrict__ x_dts,
    const float* __restrict__ Wq, const float* __restrict__ bq,
    const float* __restrict__ Wk, const float* __restrict__ bk,
    const float* __restrict__ Wv, const float* __restrict__ bv,
    const float* __restrict__ W_gd, const float* __restrict__ b_gd,
    const float* __restrict__ W_tau, const float* __restrict__ b_tau,
    const float* __restrict__ gleak, const float* __restrict__ cm,
    const float* __restrict__ W_fc, const float* __restrict__ b_fc,
    float* __restrict__ out)
{
    extern __shared__ char smraw[];
    __shared__ float sleak[32], sbtau[32];
    uint32_t* Ws   = (uint32_t*)(smraw + O_W);
    uint32_t* AsHi = (uint32_t*)(smraw + O_A);
    uint32_t* AsLo = (uint32_t*)(smraw + O_AL);
    float (*zz)[96]    = (float(*)[96])(smraw + O_Z);
    float (*sbase)[64] = (float(*)[64])(smraw + O_SB);
    float (*sz0)[96]   = (float(*)[96])(smraw + O_SZ);
    uint32_t uW  = s2u(smraw + O_W);
    uint32_t uA  = s2u(smraw + O_A);
    uint32_t uAL = s2u(smraw + O_AL);
    uint32_t uZ  = s2u(smraw + O_Z);
    uint32_t uSB = s2u(smraw + O_SB);
    uint32_t uPB = s2u(smraw + O_PB);

    int bid = blockIdx.x, tid = threadIdx.x;
    int lane = tid & 31, wid = tid >> 5;
    int gid = bid >> 4, hg = bid & 15;
    int m0 = gid * 32, h0 = hg * 32;

    // ===== prep =====
    if (tid < 32) {
        sleak[tid] = softplusf(cm[h0 + tid]) + softplusf(gleak[h0 + tid]);
        sbtau[tid] = b_tau[h0 + tid];
    }
    for (int idx = tid; idx < 96 * 256; idx += NTHR) {
        int n = idx >> 8, kq = idx & 255, k0 = kq * 2;
        float w0, w1;
        if (n < 32)      { w0 = W_gd[(64 + k0) * 1024 + h0 + n];       w1 = W_gd[(65 + k0) * 1024 + h0 + n]; }
        else if (n < 64) { w0 = W_gd[(64 + k0) * 1024 + 512 + h0 + n - 32]; w1 = W_gd[(65 + k0) * 1024 + 512 + h0 + n - 32]; }
        else             { w0 = W_tau[k0 * 512 + h0 + n - 64];         w1 = W_tau[(k0 + 1) * 512 + h0 + n - 64]; }
        float a = bfr(w0), b = bfr(w1);
        Ws[n * 260 + kq] = pack_bf2(a, b);
        g_WBLo[(hg * 96 + n) * 256 + kq] = pack_bf2(w0 - a, w1 - b);
    }
    for (int idx = tid; idx < 16 * 256; idx += NTHR) {
        int n = idx >> 8, kq = idx & 255, k0 = kq * 2;
        int nn = hg * 16 + n, ncol = nn & 127;
        const float* W = (nn < 128) ? Wk : Wv;
        float w0 = W[k0 * 128 + ncol], w1 = W[(k0 + 1) * 128 + ncol];
        float a = bfr(w0), b = bfr(w1);
        g_WKVHi[(bid * 16 + n) * 256 + kq] = pack_bf2(a, b);
        g_WKVLo[(bid * 16 + n) * 256 + kq] = pack_bf2(w0 - a, w1 - b);
    }
    for (int idx = tid; idx < 64 * 96; idx += NTHR) {
        int n = idx / 96, kq = idx - n * 96, k0 = kq * 2;
        int row0 = (k0 < 64) ? k0 : (k0 + 512);
        int col = (n < 32) ? (h0 + n) : (512 + h0 + n - 32);
        float w0 = W_gd[row0 * 1024 + col], w1 = W_gd[(row0 + 1) * 1024 + col];
        float a = bfr(w0), b = bfr(w1);
        g_WBaseHi[(bid * 64 + n) * 96 + kq] = pack_bf2(a, b);
        g_WBaseLo[(bid * 64 + n) * 96 + kq] = pack_bf2(w0 - a, w1 - b);
    }
    // precompute Q for this block's 2 batches, all t (block-local consumption)
    for (int p = 0; p < 64; p++) {
        int bt = bid * 256 + p * 4 + (tid >> 7);
        int col = tid & 127;
        float q = bq[col];
        const float* xr = &x_states[bt * DD];
#pragma unroll 16
        for (int d = 0; d < DD; d++) q += __ldg(&xr[d]) * Wq[d * AA + col];
        g_Q[bt * AA + col] = q;
    }
    for (int idx = tid; idx < 32 * HH; idx += NTHR) g_h[m0 * HH + idx] = 0.f;
    {
        int mzr = tid >> 4, czc = tid & 15;
        g_hHi[(m0 + mzr) * 256 + hg * 16 + czc] = 0;
        g_hLo[(m0 + mzr) * 256 + hg * 16 + czc] = 0;
    }
    gbar(gid);

    float hreg[2] = {0.f, 0.f}, rk1[2], rk2[2], rk3[2], dd[2];
    int kh = wid >> 3, wl = wid & 7;
    int wm = (wl >> 2) * 16, wn = (wl & 3) * 24;
    int qa = lane & 3;
    int aSel = (lane >> 4) << 2;
    int bSel = ((lane >> 3) & 1) << 2;
    int rowA_st = (wm + (lane & 15)) * 260 + aSel;
    int rowB0 = (wn + 0 * 8 + (lane & 7)) * 260 + bSel;
    int rowB1 = (wn + 1 * 8 + (lane & 7)) * 260 + bSel;
    int rowB2 = (wn + 2 * 8 + (lane & 7)) * 260 + bSel;
    long loN0 = (long)(hg * 96 + wn + 0 * 8 + (lane >> 2)) * 256 + qa;
    long loN1 = (long)(hg * 96 + wn + 1 * 8 + (lane >> 2)) * 256 + qa;
    long loN2 = (long)(hg * 96 + wn + 2 * 8 + (lane >> 2)) * 256 + qa;
    int wkn = wid & 1, wkm = (wid >> 1) & 1, wks = wid >> 2;
    int rowA_kv = (wkm * 16 + (lane & 15)) * 260 + aSel;
    int rowB_kv = (wkn * 8 + (lane & 7)) * 260 + bSel;
    int wbk2 = wid >> 3, wbm2 = (wid >> 2) & 1, wbn2 = wid & 3;
    int rowA_bs = (wbm2 * 16 + (lane & 15)) * 100 + aSel;

    for (int t = 0; t < TT; t++) {
        // ---- KV (tensorized): row t-1; A(h) preserved into stage0 ----
        if (t > 0) {
#pragma unroll
            for (int i = 0; i < 4; i++) {
                int u4 = i * 512 + tid;
                int m = u4 >> 6, q4 = u4 & 63;
                *(uint4*)&AsHi[m * 260 + q4 * 4] = ((const uint4*)&g_hHi[(m0 + m) * 256])[q4];
                *(uint4*)&AsLo[m * 260 + q4 * 4] = ((const uint4*)&g_hLo[(m0 + m) * 256])[q4];
            }
            uint32_t* Bh = (uint32_t*)(smraw + O_Z);
            uint32_t* Bl = (uint32_t*)(smraw + O_SB);
#pragma unroll
            for (int i = 0; i < 2; i++) {
                int u4 = i * 512 + tid;
                int n = u4 >> 6, q4 = u4 & 63;
                *(uint4*)&Bh[n * 260 + q4 * 4] = ((const uint4*)&g_WKVHi[(bid * 16 + n) * 256])[q4];
                *(uint4*)&Bl[n * 260 + q4 * 4] = ((const uint4*)&g_WKVLo[(bid * 16 + n) * 256])[q4];
            }
            __syncthreads();
            float acc[4] = {0.f, 0.f, 0.f, 0.f};
#pragma unroll
            for (int it = 0; it < 8; it++) {
                int kq0 = wks * 64 + it * 8;
                uint32_t ahi[4], alo[4], bhi[2], blo[2];
                ldsm4(ahi, uA  + (rowA_kv + kq0) * 4);
                ldsm4(alo, uAL + (rowA_kv + kq0) * 4);
                ldsm2(bhi, uZ  + (rowB_kv + kq0) * 4);
                ldsm2(blo, uSB + (rowB_kv + kq0) * 4);
                mma16(acc, ahi, bhi);
                mma16(acc, alo, bhi);
                mma16(acc, ahi, blo);
            }
            __syncthreads();
            float* pkv = (float*)(smraw + O_SZ);
            {
                int ml = wkm * 16 + (lane >> 2), nl = wkn * 8 + (lane & 3) * 2;
                int off = wks * 512 + ml * 16 + nl;
                pkv[off] = acc[0]; pkv[off + 1] = acc[1];
                pkv[off + 128] = acc[2]; pkv[off + 129] = acc[3];
            }
            __syncthreads();
            {
                int m = tid >> 4, n = tid & 15;
                float s = pkv[m * 16 + n] + pkv[512 + m * 16 + n] +
                          pkv[1024 + m * 16 + n] + pkv[1536 + m * 16 + n];
                if (hg < 8) {
                    int ncol = hg * 16 + n;
                    s += bk[ncol];
                    float os = __shfl_xor_sync(~0u, s, 1);
                    if (!(tid & 1))
                        g_KbT[((m0 + m) * 64 + (ncol >> 1)) * TT + (t - 1)] = pack_bf2(s, os);
                } else {
                    int ncol = (hg - 8) * 16 + n;
                    s += bv[ncol];
                    g_V[((m0 + m) * TT + (t - 1)) * AA + ncol] = s;
                }
            }
            gbar(gid);
        }

        // ---- ATTN: Q preloaded; 2-way j-split scores ----
        {
            float* aq    = (float*)(smraw + O_SZ);
            float* asc   = aq + 256;
            float* actx  = asc + 256;
            float* ared  = actx + 512;          // [2][8]
            float* spart = ared + 16;           // [2][2][128]
            int hB = tid >> 8, lt = tid & 255;
            int b = bid * 2 + hB;
            if (t == 0) {
                if (lt < 128) g_ctx[b * AA + lt] = 0.f;
            } else {
                if (lt < 128) aq[hB * 128 + lt] = g_Q[(b * TT + t) * AA + lt];
                __syncthreads();
                // scores: threads (tp, jh) — tp = t-position, jh = j half
                {
                    int tp = lt & 127, jh = lt >> 7;
                    float part = 0.f;
                    if (tp < t) {
                        const uint32_t* Kp = &g_KbT[(b * 64 + jh * 32) * TT + tp];
                        const float* qh = &aq[hB * 128 + jh * 64];
                        float dot = 0.f;
#pragma unroll 8
                        for (int j = 0; j < 32; j++) {
                            uint32_t kv = Kp[j * TT];
                            float2 f = __bfloat1622float2(*(__nv_bfloat162*)&kv);
                            dot += f.x * qh[2 * j] + f.y * qh[2 * j + 1];
                        }
                        part = dot;
                    }
                    spart[(hB * 2 + jh) * 128 + tp] = part;
                }
                __syncthreads();
                float s = -1e30f;
                if (lt < t)
                    s = (spart[hB * 256 + lt] + spart[hB * 256 + 128 + lt]) *
                        (1.f / 11.313708498984761f);
                float m = s;
#pragma unroll
                for (int o = 16; o > 0; o >>= 1) m = fmaxf(m, __shfl_xor_sync(~0u, m, o));
                if (lane == 0) ared[hB * 8 + (wid & 7)] = m;
                __syncthreads();
                m = ared[hB * 8];
#pragma unroll
                for (int i = 1; i < 8; i++) m = fmaxf(m, ared[hB * 8 + i]);
                float e = (lt < t) ? expf(s - m) : 0.f;
                float su = e;
#pragma unroll
                for (int o = 16; o > 0; o >>= 1) su += __shfl_xor_sync(~0u, su, o);
                __syncthreads();
                if (lane == 0) ared[hB * 8 + (wid & 7)] = su;
                __syncthreads();
                su = 0.f;
#pragma unroll
                for (int i = 0; i < 8; i++) su += ared[hB * 8 + i];
                if (lt < 128) asc[hB * 128 + lt] = (lt < t) ? (e / su) : 0.f;
                __syncthreads();
                {
                    int a = lt & 127, th = lt >> 7;
                    int tlim = (t + 7) & ~7;
                    float c = 0.f;
#pragma unroll 8
                    for (int sx = th; sx < tlim; sx += 2)
                        c += asc[hB * 128 + sx] * g_V[(b * TT + sx) * AA + a];
                    actx[(hB * 2 + th) * 128 + a] = c;
                }
                __syncthreads();
                if (lt < 128)
                    g_ctx[b * AA + lt] = actx[hB * 256 + lt] + actx[hB * 256 + 128 + lt];
            }
            gbar(gid);
        }

        // ---- 4 RK stages ----
        for (int stage = 0; stage < 4; stage++) {
            float acc[3][4];
#pragma unroll
            for (int s = 0; s < 3; s++)
#pragma unroll
                for (int i = 0; i < 4; i++) acc[s][i] = 0.f;

            if (stage == 0) {
                uint32_t* bAhi = (uint32_t*)(smraw + O_Z);
                uint32_t* bAlo = (uint32_t*)(smraw + O_PB);
#pragma unroll
                for (int i = 0; i < 6; i++) {
                    int idx = i * 512 + tid;
                    int m = idx / 96, kq = idx - m * 96;
                    int k0 = kq * 2;
                    float a0, a1;
                    if (kq < 32) {
                        const float* xr = &x_states[((m0 + m) * TT + t) * DD];
                        a0 = xr[k0]; a1 = xr[k0 + 1];
                    } else {
                        const float* cr = &g_ctx[(m0 + m) * AA];
                        a0 = cr[k0 - 64]; a1 = cr[k0 - 63];
                    }
                    float h0v = bfr(a0), h1v = bfr(a1);
                    bAhi[m * 100 + kq] = pack_bf2(h0v, h1v);
                    bAlo[m * 100 + kq] = pack_bf2(a0 - h0v, a1 - h1v);
                }
                __syncthreads();
                {
                    float accb[2][4];
#pragma unroll
                    for (int s = 0; s < 2; s++)
#pragma unroll
                        for (int i = 0; i < 4; i++) accb[s][i] = 0.f;
#pragma unroll
                    for (int ks = 0; ks < 6; ks++) {
                        int kq0 = wbk2 * 48 + ks * 8;
                        uint32_t ahi[4], alo[4];
                        ldsm4(ahi, uZ  + (rowA_bs + kq0) * 4);
                        ldsm4(alo, uPB + (rowA_bs + kq0) * 4);
#pragma unroll
                        for (int s = 0; s < 2; s++) {
                            int nrow = wbn2 * 16 + s * 8 + (lane >> 2);
                            long bix = (long)(bid * 64 + nrow) * 96 + kq0 + qa;
                            uint32_t bhi[2], blo[2];
                            bhi[0] = g_WBaseHi[bix]; bhi[1] = g_WBaseHi[bix + 4];
                            blo[0] = g_WBaseLo[bix]; blo[1] = g_WBaseLo[bix + 4];
                            mma16(accb[s], ahi, bhi);
                            mma16(accb[s], alo, bhi);
                            mma16(accb[s], ahi, blo);
                        }
                    }
                    __syncthreads();
                    float* pb = (float*)(smraw + O_Z);
#pragma unroll
                    for (int s = 0; s < 2; s++) {
                        int off = wbk2 * 2048 + (wbm2 * 16 + (lane >> 2)) * 64 +
                                  wbn2 * 16 + s * 8 + (lane & 3) * 2;
                        pb[off] = accb[s][0]; pb[off + 1] = accb[s][1];
                        pb[off + 512] = accb[s][2]; pb[off + 513] = accb[s][3];
                    }
                    __syncthreads();
#pragma unroll
                    for (int i = 0; i < 4; i++) {
                        int idx = i * 512 + tid;
                        int m = idx >> 6, n = idx & 63;
                        int col = (n < 32) ? (h0 + n) : (512 + h0 + n - 32);
                        sbase[m][n] = pb[m * 64 + n] + pb[2048 + m * 64 + n] + b_gd[col];
                    }
                }
                __syncthreads();
                if (t == 0) {
#pragma unroll
                    for (int i = 0; i < 4; i++) {
                        int u4 = i * 512 + tid;
                        int m = u4 >> 6, q4 = u4 & 63;
                        *(uint4*)&AsHi[m * 260 + q4 * 4] = ((const uint4*)&g_hHi[(m0 + m) * 256])[q4];
                        *(uint4*)&AsLo[m * 260 + q4 * 4] = ((const uint4*)&g_hLo[(m0 + m) * 256])[q4];
                    }
                    __syncthreads();
                }
#pragma unroll
                for (int it = 0; it < 8; it++) {
#pragma unroll
                    for (int kb2 = 0; kb2 < 16; kb2 += 8) {
                        int kq0 = kh * 128 + it * 16 + kb2;
                        uint32_t ahi[4], alo[4], bw[2], bl[2];
                        ldsm4(ahi, uA  + (rowA_st + kq0) * 4);
                        ldsm4(alo, uAL + (rowA_st + kq0) * 4);
                        ldsm2(bw, uW + (rowB0 + kq0) * 4);
                        bl[0] = g_WBLo[loN0 + kq0]; bl[1] = g_WBLo[loN0 + kq0 + 4];
                        mma16(acc[0], ahi, bw); mma16(acc[0], alo, bw); mma16(acc[0], ahi, bl);
                        ldsm2(bw, uW + (rowB1 + kq0) * 4);
                        bl[0] = g_WBLo[loN1 + kq0]; bl[1] = g_WBLo[loN1 + kq0 + 4];
                        mma16(acc[1], ahi, bw); mma16(acc[1], alo, bw); mma16(acc[1], ahi, bl);
                        ldsm2(bw, uW + (rowB2 + kq0) * 4);
                        bl[0] = g_WBLo[loN2 + kq0]; bl[1] = g_WBLo[loN2 + kq0 + 4];
                        mma16(acc[2], ahi, bw); mma16(acc[2], alo, bw); mma16(acc[2], ahi, bl);
                    }
                }
                __syncthreads();
            } else {
                const uint32_t* Dg = (stage == 2) ? g_dB : g_dA;
#pragma unroll
                for (int i = 0; i < 4; i++) {
                    int idx = i * 512 + tid;
                    int m = idx >> 6, q4 = idx & 63;
                    *(uint4*)&AsHi[m * 260 + q4 * 4] = ((const uint4*)&Dg[(m0 + m) * 256])[q4];
                }
                __syncthreads();
#pragma unroll
                for (int it = 0; it < 8; it++) {
#pragma unroll
                    for (int kb2 = 0; kb2 < 16; kb2 += 8) {
                        int kq0 = kh * 128 + it * 16 + kb2;
                        uint32_t ahi[4], bw[2];
                        ldsm4(ahi, uA + (rowA_st + kq0) * 4);
                        ldsm2(bw, uW + (rowB0 + kq0) * 4);
                        mma16(acc[0], ahi, bw);
                        ldsm2(bw, uW + (rowB1 + kq0) * 4);
                        mma16(acc[1], ahi, bw);
                        ldsm2(bw, uW + (rowB2 + kq0) * 4);
                        mma16(acc[2], ahi, bw);
                    }
                }
                __syncthreads();
            }

            {
                int rr = wm + (lane >> 2), cc = wn + (lane & 3) * 2;
#pragma unroll
                for (int s = 0; s < 3; s++) {
                    zz[kh * 32 + rr][cc + s * 8]         = acc[s][0];
                    zz[kh * 32 + rr][cc + s * 8 + 1]     = acc[s][1];
                    zz[kh * 32 + rr + 8][cc + s * 8]     = acc[s][2];
                    zz[kh * 32 + rr + 8][cc + s * 8 + 1] = acc[s][3];
                }
            }
            __syncthreads();
            if (stage == 0) {
#pragma unroll
                for (int i = 0; i < 6; i++) {
                    int idx = i * 512 + tid;
                    int bl = idx / 96, c = idx - bl * 96;
                    sz0[bl][c] = zz[bl][c] + zz[32 + bl][c];
                }
                __syncthreads();
            }

#pragma unroll
            for (int p = 0; p < 2; p++) {
                int idx = p * 512 + tid;
                int bl = idx >> 5, hh = idx & 31;
                int b = m0 + bl;
                float zg, zdn, zt;
                if (stage == 0) {
                    zg = sz0[bl][hh]; zdn = sz0[bl][32 + hh]; zt = sz0[bl][64 + hh];
                } else {
                    zg  = sz0[bl][hh]      + zz[bl][hh]      + zz[32 + bl][hh];
                    zdn = sz0[bl][32 + hh] + zz[bl][32 + hh] + zz[32 + bl][32 + hh];
                    zt  = sz0[bl][64 + hh] + zz[bl][64 + hh] + zz[32 + bl][64 + hh];
                }
                float gate = zg + sbase[bl][hh];
                float dyn  = zdn + sbase[bl][32 + hh];
                float tau  = softplusf(zt + sbtau[hh]);
                float hsv  = (stage == 0) ? hreg[p] : (hreg[p] + dd[p]);
                float kd   = (sigmoidf(gate) * tanhf(dyn) - hsv) / (tau + sleak[hh] + 1e-6f);
                float dt   = x_dts[b * TT + t];
                if (stage == 3) {
                    hreg[p] += dt * (rk1[p] + 3.f * rk2[p] + 3.f * rk3[p] + kd) * 0.125f;
                    g_h[b * HH + h0 + hh] = hreg[p];
                    float hi = bfr(hreg[p]);
                    float lo = hreg[p] - hi;
                    float ohi = __shfl_xor_sync(~0u, hi, 1);
                    float olo = __shfl_xor_sync(~0u, lo, 1);
                    if (!(tid & 1)) {
                        g_hHi[b * 256 + ((h0 + hh) >> 1)] = pack_bf2(hi, ohi);
                        g_hLo[b * 256 + ((h0 + hh) >> 1)] = pack_bf2(lo, olo);
                    }
                } else {
                    float dnew;
                    if (stage == 0)      { rk1[p] = kd; dnew = dt * kd * (1.f / 3.f); }
                    else if (stage == 1) { rk2[p] = kd; dnew = dt * (kd - rk1[p] * (1.f / 3.f)); }
                    else                 { rk3[p] = kd; dnew = dt * (rk1[p] - rk2[p] + kd); }
                    dd[p] = dnew;
                    float oth = __shfl_xor_sync(~0u, dnew, 1);
                    if (!(tid & 1)) {
                        uint32_t pk = pack_bf2(dnew, oth);
                        if (stage == 1) g_dB[b * 256 + ((h0 + hh) >> 1)] = pk;
                        else            g_dA[b * 256 + ((h0 + hh) >> 1)] = pk;
                    }
                }
            }
            gbar(gid);
        }
    }

    // ===== final projection =====
    {
        int b = bid * 2 + (tid >> 8);
        int lt = tid & 255;
        if (lt < OO) {
            float acc = b_fc[lt];
#pragma unroll 8
            for (int k = 0; k < HH; k++) acc += g_h[b * HH + k] * W_fc[k * OO + lt];
            out[b * OO + lt] = acc;
        }
    }
}

extern "C" void kernel_launch(void* const* d_in, const int* in_sizes, int n_in,
                              void* d_out, int out_size) {
    const float* x_states = (const float*)d_in[0];
    const float* x_dts    = (const float*)d_in[1];
    const float* Wq = (const float*)d_in[2];  const float* bq = (const float*)d_in[3];
    const float* Wk = (const float*)d_in[4];  const float* bk = (const float*)d_in[5];
    const float* Wv = (const float*)d_in[6];  const float* bv = (const float*)d_in[7];
    const float* W_gd = (const float*)d_in[8]; const float* b_gd = (const float*)d_in[9];
    const float* W_tau = (const float*)d_in[10]; const float* b_tau = (const float*)d_in[11];
    const float* gleak = (const float*)d_in[12]; const float* cm = (const float*)d_in[13];
    const float* W_fc = (const float*)d_in[14]; const float* b_fc = (const float*)d_in[15];
    float* out = (float*)d_out;

    cudaFuncSetAttribute(mega, cudaFuncAttributeMaxDynamicSharedMemorySize, SMEM_BYTES);
    mega<<<NBLK, NTHR, SMEM_BYTES>>>(x_states, x_dts, Wq, bq, Wk, bk, Wv, bv,
                                     W_gd, b_gd, W_tau, b_tau, gleak, cm,
                                     W_fc, b_fc, out);
}

// round 16
// speedup vs baseline: 1.0606x; 1.0181x over previous
#include <cuda_runtime.h>
#include <cuda_bf16.h>
#include <math.h>
#include <stdint.h>

#define BB 256
#define TT 128
#define DD 64
#define HH 512
#define AA 128
#define OO 32
#define NBLK 128
#define NTHR 512

__device__ uint32_t g_KbT[BB * 64 * TT];      // K transposed bf16x2: [(b*64+j)*128 + t]
__device__ float g_V[BB * TT * AA];
__device__ float g_Q[BB * TT * AA];
__device__ uint32_t g_WBLo[16 * 96 * 256];    // stage lo residual [hg][n][kq]
__device__ uint32_t g_WKV2Hi[NBLK * 256 * 16]; // per-block KV slice [bid][n][kq], k=h0..h0+31
__device__ uint32_t g_WKV2Lo[NBLK * 256 * 16];
__device__ uint32_t g_WBaseHi[NBLK * 64 * 96];
__device__ uint32_t g_WBaseLo[NBLK * 64 * 96];
__device__ float g_part[NBLK * 32 * 256];      // KV partials [bid][m][n]
__device__ float g_ctx[BB * AA];
__device__ float g_h[BB * HH];
__device__ uint32_t g_hHi[BB * 256];
__device__ uint32_t g_hLo[BB * 256];
__device__ uint32_t g_dA[BB * 256];
__device__ uint32_t g_dB[BB * 256];
__device__ unsigned g_cnt[8 * 32];
__device__ unsigned g_gen[8 * 32];

__device__ __forceinline__ float softplusf(float x) {
    return (x > 20.f) ? x : log1pf(expf(x));
}
__device__ __forceinline__ float sigmoidf(float x) {
    return 1.f / (1.f + expf(-x));
}
__device__ __forceinline__ float bfr(float x) {
    return __bfloat162float(__float2bfloat16(x));
}
__device__ __forceinline__ void mma16(float* d, const uint32_t* a, const uint32_t* b) {
    asm volatile(
        "mma.sync.aligned.m16n8k16.row.col.f32.bf16.bf16.f32 "
        "{%0,%1,%2,%3},{%4,%5,%6,%7},{%8,%9},{%0,%1,%2,%3};"
        : "+f"(d[0]), "+f"(d[1]), "+f"(d[2]), "+f"(d[3])
        : "r"(a[0]), "r"(a[1]), "r"(a[2]), "r"(a[3]), "r"(b[0]), "r"(b[1]));
}
__device__ __forceinline__ uint32_t pack_bf2(float a, float b) {
    __nv_bfloat162 t = __floats2bfloat162_rn(a, b);
    return *(uint32_t*)&t;
}
__device__ __forceinline__ uint32_t s2u(const void* p) {
    return (uint32_t)__cvta_generic_to_shared(p);
}
__device__ __forceinline__ void ldsm4(uint32_t* r, uint32_t a) {
    asm volatile("ldmatrix.sync.aligned.m8n8.x4.shared.b16 {%0,%1,%2,%3}, [%4];"
                 : "=r"(r[0]), "=r"(r[1]), "=r"(r[2]), "=r"(r[3]) : "r"(a));
}
__device__ __forceinline__ void ldsm2(uint32_t* r, uint32_t a) {
    asm volatile("ldmatrix.sync.aligned.m8n8.x2.shared.b16 {%0,%1}, [%2];"
                 : "=r"(r[0]), "=r"(r[1]) : "r"(a));
}

__device__ __forceinline__ void gbar(int idx) {
    __syncthreads();
    if (threadIdx.x == 0) {
        unsigned* cntp = &g_cnt[idx * 32];
        unsigned* genp = &g_gen[idx * 32];
        unsigned gen;
        asm volatile("ld.acquire.gpu.global.u32 %0, [%1];" : "=r"(gen) : "l"(genp));
        unsigned old;
        asm volatile("atom.release.gpu.global.add.u32 %0, [%1], %2;"
                     : "=r"(old) : "l"(cntp), "r"(1u));
        if (old == 15u) {
            asm volatile("st.relaxed.gpu.global.u32 [%0], %1;" :: "l"(cntp), "r"(0u));
            asm volatile("st.release.gpu.global.u32 [%0], %1;" :: "l"(genp), "r"(gen + 1u));
        } else {
            unsigned cur = gen;
            while (cur == gen) {
                __nanosleep(32);
                asm volatile("ld.acquire.gpu.global.u32 %0, [%1];" : "=r"(cur) : "l"(genp));
            }
        }
    }
    __syncthreads();
}

#define O_W  0
#define O_A  99840
#define O_AL 133120
#define O_Z  166400
#define O_SB 190976
#define O_SZ 199168
#define O_PB 211456
#define SMEM_BYTES 224256

__global__ void __launch_bounds__(NTHR, 1) mega(
    const float* __restrict__ x_states, const float* __restrict__ x_dts,
    const float* __restrict__ Wq, const float* __restrict__ bq,
    const float* __restrict__ Wk, const float* __restrict__ bk,
    const float* __restrict__ Wv, const float* __restrict__ bv,
    const float* __restrict__ W_gd, const float* __restrict__ b_gd,
    const float* __restrict__ W_tau, const float* __restrict__ b_tau,
    const float* __restrict__ gleak, const float* __restrict__ cm,
    const float* __restrict__ W_fc, const float* __restrict__ b_fc,
    float* __restrict__ out)
{
    extern __shared__ char smraw[];
    __shared__ float sleak[32], sbtau[32];
    uint32_t* Ws   = (uint32_t*)(smraw + O_W);
    uint32_t* AsHi = (uint32_t*)(smraw + O_A);
    uint32_t* AsLo = (uint32_t*)(smraw + O_AL);
    float (*zz)[96]    = (float(*)[96])(smraw + O_Z);
    float (*sbase)[64] = (float(*)[64])(smraw + O_SB);
    float (*sz0)[96]   = (float(*)[96])(smraw + O_SZ);
    uint32_t uW  = s2u(smraw + O_W);
    uint32_t uA  = s2u(smraw + O_A);
    uint32_t uAL = s2u(smraw + O_AL);
    uint32_t uZ  = s2u(smraw + O_Z);
    uint32_t uPB = s2u(smraw + O_PB);

    int bid = blockIdx.x, tid = threadIdx.x;
    int lane = tid & 31, wid = tid >> 5;
    int gid = bid >> 4, hg = bid & 15;
    int m0 = gid * 32, h0 = hg * 32;

    // ===== prep =====
    if (tid < 32) {
        sleak[tid] = softplusf(cm[h0 + tid]) + softplusf(gleak[h0 + tid]);
        sbtau[tid] = b_tau[h0 + tid];
    }
    for (int idx = tid; idx < 96 * 256; idx += NTHR) {
        int n = idx >> 8, kq = idx & 255, k0 = kq * 2;
        float w0, w1;
        if (n < 32)      { w0 = W_gd[(64 + k0) * 1024 + h0 + n];       w1 = W_gd[(65 + k0) * 1024 + h0 + n]; }
        else if (n < 64) { w0 = W_gd[(64 + k0) * 1024 + 512 + h0 + n - 32]; w1 = W_gd[(65 + k0) * 1024 + 512 + h0 + n - 32]; }
        else             { w0 = W_tau[k0 * 512 + h0 + n - 64];         w1 = W_tau[(k0 + 1) * 512 + h0 + n - 64]; }
        float a = bfr(w0), b = bfr(w1);
        Ws[n * 260 + kq] = pack_bf2(a, b);
        g_WBLo[(hg * 96 + n) * 256 + kq] = pack_bf2(w0 - a, w1 - b);
    }
    for (int idx = tid; idx < 256 * 16; idx += NTHR) {   // KV slice: k = h0..h0+31
        int n = idx >> 4, kq = idx & 15;
        int k0 = h0 + 2 * kq, ncol = n & 127;
        const float* W = (n < 128) ? Wk : Wv;
        float w0 = W[k0 * 128 + ncol], w1 = W[(k0 + 1) * 128 + ncol];
        float a = bfr(w0), b = bfr(w1);
        g_WKV2Hi[bid * 4096 + idx] = pack_bf2(a, b);
        g_WKV2Lo[bid * 4096 + idx] = pack_bf2(w0 - a, w1 - b);
    }
    for (int idx = tid; idx < 64 * 96; idx += NTHR) {
        int n = idx / 96, kq = idx - n * 96, k0 = kq * 2;
        int row0 = (k0 < 64) ? k0 : (k0 + 512);
        int col = (n < 32) ? (h0 + n) : (512 + h0 + n - 32);
        float w0 = W_gd[row0 * 1024 + col], w1 = W_gd[(row0 + 1) * 1024 + col];
        float a = bfr(w0), b = bfr(w1);
        g_WBaseHi[(bid * 64 + n) * 96 + kq] = pack_bf2(a, b);
        g_WBaseLo[(bid * 64 + n) * 96 + kq] = pack_bf2(w0 - a, w1 - b);
    }
    for (int p = 0; p < 64; p++) {          // precompute Q (block-local use)
        int bt = bid * 256 + p * 4 + (tid >> 7);
        int col = tid & 127;
        float q = bq[col];
        const float* xr = &x_states[bt * DD];
#pragma unroll 16
        for (int d = 0; d < DD; d++) q += __ldg(&xr[d]) * Wq[d * AA + col];
        g_Q[bt * AA + col] = q;
    }
    for (int idx = tid; idx < 32 * HH; idx += NTHR) g_h[m0 * HH + idx] = 0.f;
    {
        int mzr = tid >> 4, czc = tid & 15;
        g_hHi[(m0 + mzr) * 256 + hg * 16 + czc] = 0;
        g_hLo[(m0 + mzr) * 256 + hg * 16 + czc] = 0;
    }
    gbar(gid);

    float hreg[2] = {0.f, 0.f}, rk1[2], rk2[2], rk3[2], dd[2];
    int kh = wid >> 3, wl = wid & 7;
    int wm = (wl >> 2) * 16, wn = (wl & 3) * 24;
    int qa = lane & 3;
    int aSel = (lane >> 4) << 2;
    int bSel = ((lane >> 3) & 1) << 2;
    int rowA_st = (wm + (lane & 15)) * 260 + aSel;
    int rowB0 = (wn + 0 * 8 + (lane & 7)) * 260 + bSel;
    int rowB1 = (wn + 1 * 8 + (lane & 7)) * 260 + bSel;
    int rowB2 = (wn + 2 * 8 + (lane & 7)) * 260 + bSel;
    long loN0 = (long)(hg * 96 + wn + 0 * 8 + (lane >> 2)) * 256 + qa;
    long loN1 = (long)(hg * 96 + wn + 1 * 8 + (lane >> 2)) * 256 + qa;
    long loN2 = (long)(hg * 96 + wn + 2 * 8 + (lane >> 2)) * 256 + qa;
    int wbk2 = wid >> 3, wbm2 = (wid >> 2) & 1, wbn2 = wid & 3;
    int rowA_bs = (wbm2 * 16 + (lane & 15)) * 100 + aSel;
    // KV-partial warp map: 8 n-groups x 2 m-halves
    int wnn = wid >> 1, wkm2 = wid & 1;
    int rowA_pk = (wkm2 * 16 + (lane & 15)) * 260 + aSel;

    for (int t = 0; t < TT; t++) {
        // ---- ATTN phase: sum KV partials (row t-1), stage A(h), attention ----
        {
            // stage A(h) hi/lo for stage0 (region untouched by attn scratch)
#pragma unroll
            for (int i = 0; i < 4; i++) {
                int u4 = i * 512 + tid;
                int m = u4 >> 6, q4 = u4 & 63;
                *(uint4*)&AsHi[m * 260 + q4 * 4] = ((const uint4*)&g_hHi[(m0 + m) * 256])[q4];
                *(uint4*)&AsLo[m * 260 + q4 * 4] = ((const uint4*)&g_hLo[(m0 + m) * 256])[q4];
            }
            float* aq    = (float*)(smraw + O_SZ);
            float* asc   = aq + 256;
            float* actx  = asc + 256;
            float* ared  = actx + 512;
            float* spart = ared + 16;
            int hB = tid >> 8, lt = tid & 255;
            int b = bid * 2 + hB;
            if (t == 0) {
                if (lt < 128) g_ctx[b * AA + lt] = 0.f;
            } else {
                // sum 16 partials for this block's own 2 batches (deterministic)
                {
                    int n = lt;
                    int m = hg * 2 + hB;
                    const float* pp = &g_part[(gid * 16) * 8192 + m * 256 + n];
                    float s = 0.f;
#pragma unroll
                    for (int q = 0; q < 16; q++) s += pp[q * 8192];
                    if (n < 128) {
                        s += bk[n];
                        float os = __shfl_xor_sync(~0u, s, 1);
                        if (!(tid & 1))
                            g_KbT[(b * 64 + (n >> 1)) * TT + (t - 1)] = pack_bf2(s, os);
                    } else {
                        g_V[(b * TT + (t - 1)) * AA + (n - 128)] = s + bv[n - 128];
                    }
                }
                __syncthreads();
                if (lt < 128) aq[hB * 128 + lt] = g_Q[(b * TT + t) * AA + lt];
                __syncthreads();
                {
                    int tp = lt & 127, jh = lt >> 7;
                    float part = 0.f;
                    if (tp < t) {
                        const uint32_t* Kp = &g_KbT[(b * 64 + jh * 32) * TT + tp];
                        const float* qh = &aq[hB * 128 + jh * 64];
                        float dot = 0.f;
#pragma unroll 8
                        for (int j = 0; j < 32; j++) {
                            uint32_t kv = Kp[j * TT];
                            float2 f = __bfloat1622float2(*(__nv_bfloat162*)&kv);
                            dot += f.x * qh[2 * j] + f.y * qh[2 * j + 1];
                        }
                        part = dot;
                    }
                    spart[(hB * 2 + jh) * 128 + tp] = part;
                }
                __syncthreads();
                float s = -1e30f;
                if (lt < t)
                    s = (spart[hB * 256 + lt] + spart[hB * 256 + 128 + lt]) *
                        (1.f / 11.313708498984761f);
                float m = s;
#pragma unroll
                for (int o = 16; o > 0; o >>= 1) m = fmaxf(m, __shfl_xor_sync(~0u, m, o));
                if (lane == 0) ared[hB * 8 + (wid & 7)] = m;
                __syncthreads();
                m = ared[hB * 8];
#pragma unroll
                for (int i = 1; i < 8; i++) m = fmaxf(m, ared[hB * 8 + i]);
                float e = (lt < t) ? expf(s - m) : 0.f;
                float su = e;
#pragma unroll
                for (int o = 16; o > 0; o >>= 1) su += __shfl_xor_sync(~0u, su, o);
                __syncthreads();
                if (lane == 0) ared[hB * 8 + (wid & 7)] = su;
                __syncthreads();
                su = 0.f;
#pragma unroll
                for (int i = 0; i < 8; i++) su += ared[hB * 8 + i];
                if (lt < 128) asc[hB * 128 + lt] = (lt < t) ? (e / su) : 0.f;
                __syncthreads();
                {
                    int a = lt & 127, th = lt >> 7;
                    int tlim = (t + 7) & ~7;
                    float c = 0.f;
#pragma unroll 8
                    for (int sx = th; sx < tlim; sx += 2)
                        c += asc[hB * 128 + sx] * g_V[(b * TT + sx) * AA + a];
                    actx[(hB * 2 + th) * 128 + a] = c;
                }
                __syncthreads();
                if (lt < 128)
                    g_ctx[b * AA + lt] = actx[hB * 256 + lt] + actx[hB * 256 + 128 + lt];
            }
            gbar(gid);
        }

        // ---- 4 RK stages ----
        for (int stage = 0; stage < 4; stage++) {
            float acc[3][4];
#pragma unroll
            for (int s = 0; s < 3; s++)
#pragma unroll
                for (int i = 0; i < 4; i++) acc[s][i] = 0.f;

            if (stage == 0) {
                uint32_t* bAhi = (uint32_t*)(smraw + O_Z);
                uint32_t* bAlo = (uint32_t*)(smraw + O_PB);
#pragma unroll
                for (int i = 0; i < 6; i++) {
                    int idx = i * 512 + tid;
                    int m = idx / 96, kq = idx - m * 96;
                    int k0 = kq * 2;
                    float a0, a1;
                    if (kq < 32) {
                        const float* xr = &x_states[((m0 + m) * TT + t) * DD];
                        a0 = xr[k0]; a1 = xr[k0 + 1];
                    } else {
                        const float* cr = &g_ctx[(m0 + m) * AA];
                        a0 = cr[k0 - 64]; a1 = cr[k0 - 63];
                    }
                    float h0v = bfr(a0), h1v = bfr(a1);
                    bAhi[m * 100 + kq] = pack_bf2(h0v, h1v);
                    bAlo[m * 100 + kq] = pack_bf2(a0 - h0v, a1 - h1v);
                }
                __syncthreads();
                {
                    float accb[2][4];
#pragma unroll
                    for (int s = 0; s < 2; s++)
#pragma unroll
                        for (int i = 0; i < 4; i++) accb[s][i] = 0.f;
#pragma unroll
                    for (int ks = 0; ks < 6; ks++) {
                        int kq0 = wbk2 * 48 + ks * 8;
                        uint32_t ahi[4], alo[4];
                        ldsm4(ahi, uZ  + (rowA_bs + kq0) * 4);
                        ldsm4(alo, uPB + (rowA_bs + kq0) * 4);
#pragma unroll
                        for (int s = 0; s < 2; s++) {
                            int nrow = wbn2 * 16 + s * 8 + (lane >> 2);
                            long bix = (long)(bid * 64 + nrow) * 96 + kq0 + qa;
                            uint32_t bhi[2], blo[2];
                            bhi[0] = g_WBaseHi[bix]; bhi[1] = g_WBaseHi[bix + 4];
                            blo[0] = g_WBaseLo[bix]; blo[1] = g_WBaseLo[bix + 4];
                            mma16(accb[s], ahi, bhi);
                            mma16(accb[s], alo, bhi);
                            mma16(accb[s], ahi, blo);
                        }
                    }
                    __syncthreads();
                    float* pb = (float*)(smraw + O_Z);
#pragma unroll
                    for (int s = 0; s < 2; s++) {
                        int off = wbk2 * 2048 + (wbm2 * 16 + (lane >> 2)) * 64 +
                                  wbn2 * 16 + s * 8 + (lane & 3) * 2;
                        pb[off] = accb[s][0]; pb[off + 1] = accb[s][1];
                        pb[off + 512] = accb[s][2]; pb[off + 513] = accb[s][3];
                    }
                    __syncthreads();
#pragma unroll
                    for (int i = 0; i < 4; i++) {
                        int idx = i * 512 + tid;
                        int m = idx >> 6, n = idx & 63;
                        int col = (n < 32) ? (h0 + n) : (512 + h0 + n - 32);
                        sbase[m][n] = pb[m * 64 + n] + pb[2048 + m * 64 + n] + b_gd[col];
                    }
                }
                __syncthreads();
#pragma unroll
                for (int it = 0; it < 8; it++) {
#pragma unroll
                    for (int kb2 = 0; kb2 < 16; kb2 += 8) {
                        int kq0 = kh * 128 + it * 16 + kb2;
                        uint32_t ahi[4], alo[4], bw[2], bl[2];
                        ldsm4(ahi, uA  + (rowA_st + kq0) * 4);
                        ldsm4(alo, uAL + (rowA_st + kq0) * 4);
                        ldsm2(bw, uW + (rowB0 + kq0) * 4);
                        bl[0] = g_WBLo[loN0 + kq0]; bl[1] = g_WBLo[loN0 + kq0 + 4];
                        mma16(acc[0], ahi, bw); mma16(acc[0], alo, bw); mma16(acc[0], ahi, bl);
                        ldsm2(bw, uW + (rowB1 + kq0) * 4);
                        bl[0] = g_WBLo[loN1 + kq0]; bl[1] = g_WBLo[loN1 + kq0 + 4];
                        mma16(acc[1], ahi, bw); mma16(acc[1], alo, bw); mma16(acc[1], ahi, bl);
                        ldsm2(bw, uW + (rowB2 + kq0) * 4);
                        bl[0] = g_WBLo[loN2 + kq0]; bl[1] = g_WBLo[loN2 + kq0 + 4];
                        mma16(acc[2], ahi, bw); mma16(acc[2], alo, bw); mma16(acc[2], ahi, bl);
                    }
                }
                __syncthreads();
            } else {
                const uint32_t* Dg = (stage == 2) ? g_dB : g_dA;
#pragma unroll
                for (int i = 0; i < 4; i++) {
                    int idx = i * 512 + tid;
                    int m = idx >> 6, q4 = idx & 63;
                    *(uint4*)&AsHi[m * 260 + q4 * 4] = ((const uint4*)&Dg[(m0 + m) * 256])[q4];
                }
                __syncthreads();
#pragma unroll
                for (int it = 0; it < 8; it++) {
#pragma unroll
                    for (int kb2 = 0; kb2 < 16; kb2 += 8) {
                        int kq0 = kh * 128 + it * 16 + kb2;
                        uint32_t ahi[4], bw[2];
                        ldsm4(ahi, uA + (rowA_st + kq0) * 4);
                        ldsm2(bw, uW + (rowB0 + kq0) * 4);
                        mma16(acc[0], ahi, bw);
                        ldsm2(bw, uW + (rowB1 + kq0) * 4);
                        mma16(acc[1], ahi, bw);
                        ldsm2(bw, uW + (rowB2 + kq0) * 4);
                        mma16(acc[2], ahi, bw);
                    }
                }
                __syncthreads();
            }

            {
                int rr = wm + (lane >> 2), cc = wn + (lane & 3) * 2;
#pragma unroll
                for (int s = 0; s < 3; s++) {
                    zz[kh * 32 + rr][cc + s * 8]         = acc[s][0];
                    zz[kh * 32 + rr][cc + s * 8 + 1]     = acc[s][1];
                    zz[kh * 32 + rr + 8][cc + s * 8]     = acc[s][2];
                    zz[kh * 32 + rr + 8][cc + s * 8 + 1] = acc[s][3];
                }
            }
            __syncthreads();
            if (stage == 0) {
#pragma unroll
                for (int i = 0; i < 6; i++) {
                    int idx = i * 512 + tid;
                    int bl = idx / 96, c = idx - bl * 96;
                    sz0[bl][c] = zz[bl][c] + zz[32 + bl][c];
                }
                __syncthreads();
            }

#pragma unroll
            for (int p = 0; p < 2; p++) {
                int idx = p * 512 + tid;
                int bl = idx >> 5, hh = idx & 31;
                int b = m0 + bl;
                float zg, zdn, zt;
                if (stage == 0) {
                    zg = sz0[bl][hh]; zdn = sz0[bl][32 + hh]; zt = sz0[bl][64 + hh];
                } else {
                    zg  = sz0[bl][hh]      + zz[bl][hh]      + zz[32 + bl][hh];
                    zdn = sz0[bl][32 + hh] + zz[bl][32 + hh] + zz[32 + bl][32 + hh];
                    zt  = sz0[bl][64 + hh] + zz[bl][64 + hh] + zz[32 + bl][64 + hh];
                }
                float gate = zg + sbase[bl][hh];
                float dyn  = zdn + sbase[bl][32 + hh];
                float tau  = softplusf(zt + sbtau[hh]);
                float hsv  = (stage == 0) ? hreg[p] : (hreg[p] + dd[p]);
                float kd   = (sigmoidf(gate) * tanhf(dyn) - hsv) / (tau + sleak[hh] + 1e-6f);
                float dt   = x_dts[b * TT + t];
                if (stage == 3) {
                    hreg[p] += dt * (rk1[p] + 3.f * rk2[p] + 3.f * rk3[p] + kd) * 0.125f;
                    g_h[b * HH + h0 + hh] = hreg[p];
                    float hi = bfr(hreg[p]);
                    float lo = hreg[p] - hi;
                    float ohi = __shfl_xor_sync(~0u, hi, 1);
                    float olo = __shfl_xor_sync(~0u, lo, 1);
                    if (!(tid & 1)) {
                        uint32_t pkhi = pack_bf2(hi, ohi), pklo = pack_bf2(lo, olo);
                        g_hHi[b * 256 + ((h0 + hh) >> 1)] = pkhi;
                        g_hLo[b * 256 + ((h0 + hh) >> 1)] = pklo;
                        AsHi[bl * 260 + (hh >> 1)] = pkhi;   // local h slice for KV partial
                        AsLo[bl * 260 + (hh >> 1)] = pklo;
                    }
                } else {
                    float dnew;
                    if (stage == 0)      { rk1[p] = kd; dnew = dt * kd * (1.f / 3.f); }
                    else if (stage == 1) { rk2[p] = kd; dnew = dt * (kd - rk1[p] * (1.f / 3.f)); }
                    else                 { rk3[p] = kd; dnew = dt * (rk1[p] - rk2[p] + kd); }
                    dd[p] = dnew;
                    float oth = __shfl_xor_sync(~0u, dnew, 1);
                    if (!(tid & 1)) {
                        uint32_t pk = pack_bf2(dnew, oth);
                        if (stage == 1) g_dB[b * 256 + ((h0 + hh) >> 1)] = pk;
                        else            g_dA[b * 256 + ((h0 + hh) >> 1)] = pk;
                    }
                }
            }

            // ---- stage3 tail: KV partial GEMM (M32 x N256 x K32) ----
            if (stage == 3) {
                __syncthreads();
                float ac[4][4];
#pragma unroll
                for (int s = 0; s < 4; s++)
#pragma unroll
                    for (int i = 0; i < 4; i++) ac[s][i] = 0.f;
#pragma unroll
                for (int kst = 0; kst < 2; kst++) {
                    uint32_t ahi[4], alo[4];
                    ldsm4(ahi, uA  + (rowA_pk + kst * 8) * 4);
                    ldsm4(alo, uAL + (rowA_pk + kst * 8) * 4);
#pragma unroll
                    for (int nt2 = 0; nt2 < 4; nt2++) {
                        int nrow = wnn * 32 + nt2 * 8 + (lane >> 2);
                        long wix = (long)(bid * 256 + nrow) * 16 + kst * 8 + qa;
                        uint32_t bh[2], bl2[2];
                        bh[0] = g_WKV2Hi[wix]; bh[1] = g_WKV2Hi[wix + 4];
                        bl2[0] = g_WKV2Lo[wix]; bl2[1] = g_WKV2Lo[wix + 4];
                        mma16(ac[nt2], ahi, bh);
                        mma16(ac[nt2], alo, bh);
                        mma16(ac[nt2], ahi, bl2);
                    }
                }
                float* gp = &g_part[bid * 8192];
#pragma unroll
                for (int nt2 = 0; nt2 < 4; nt2++) {
                    int m = wkm2 * 16 + (lane >> 2);
                    int n = wnn * 32 + nt2 * 8 + (lane & 3) * 2;
                    *(float2*)&gp[m * 256 + n]       = make_float2(ac[nt2][0], ac[nt2][1]);
                    *(float2*)&gp[(m + 8) * 256 + n] = make_float2(ac[nt2][2], ac[nt2][3]);
                }
            }
            gbar(gid);
        }
    }

    // ===== final projection =====
    {
        int b = bid * 2 + (tid >> 8);
        int lt = tid & 255;
        if (lt < OO) {
            float acc = b_fc[lt];
#pragma unroll 8
            for (int k = 0; k < HH; k++) acc += g_h[b * HH + k] * W_fc[k * OO + lt];
            out[b * OO + lt] = acc;
        }
    }
}

extern "C" void kernel_launch(void* const* d_in, const int* in_sizes, int n_in,
                              void* d_out, int out_size) {
    const float* x_states = (const float*)d_in[0];
    const float* x_dts    = (const float*)d_in[1];
    const float* Wq = (const float*)d_in[2];  const float* bq = (const float*)d_in[3];
    const float* Wk = (const float*)d_in[4];  const float* bk = (const float*)d_in[5];
    const float* Wv = (const float*)d_in[6];  const float* bv = (const float*)d_in[7];
    const float* W_gd = (const float*)d_in[8]; const float* b_gd = (const float*)d_in[9];
    const float* W_tau = (const float*)d_in[10]; const float* b_tau = (const float*)d_in[11];
    const float* gleak = (const float*)d_in[12]; const float* cm = (const float*)d_in[13];
    const float* W_fc = (const float*)d_in[14]; const float* b_fc = (const float*)d_in[15];
    float* out = (float*)d_out;

    cudaFuncSetAttribute(mega, cudaFuncAttributeMaxDynamicSharedMemorySize, SMEM_BYTES);
    mega<<<NBLK, NTHR, SMEM_BYTES>>>(x_states, x_dts, Wq, bq, Wk, bk, Wv, bv,
                                     W_gd, b_gd, W_tau, b_tau, gleak, cm,
                                     W_fc, b_fc, out);
}

// round 17
// speedup vs baseline: 1.0760x; 1.0146x over previous
#include <cuda_runtime.h>
#include <cuda_bf16.h>
#include <math.h>
#include <stdint.h>

#define BB 256
#define TT 128
#define DD 64
#define HH 512
#define AA 128
#define OO 32
#define NBLK 128
#define NTHR 512

__device__ uint32_t g_KbT[BB * 64 * TT];       // K transposed bf16x2
__device__ float g_V[BB * TT * AA];
__device__ float g_Q[BB * TT * AA];
__device__ uint32_t g_WBLo[16 * 96 * 256];
__device__ uint32_t g_WKV2Hi[NBLK * 256 * 16];
__device__ uint32_t g_WKV2Lo[NBLK * 256 * 16];
__device__ uint32_t g_WBaseHi[NBLK * 64 * 96];
__device__ uint32_t g_WBaseLo[NBLK * 64 * 96];
__device__ float g_part[NBLK * 32 * 256];
__device__ float g_ctx[BB * AA];
__device__ float g_h[BB * HH];
__device__ uint32_t g_hHi[BB * 256];
__device__ uint32_t g_hLo[BB * 256];
__device__ uint32_t g_dA[BB * 256];
__device__ uint32_t g_dB[BB * 256];
__device__ unsigned g_cnt[8 * 32];
__device__ unsigned g_gen[8 * 32];

__device__ __forceinline__ float softplusf(float x) {
    return (x > 20.f) ? x : log1pf(expf(x));
}
__device__ __forceinline__ float sigmoidf(float x) {
    return 1.f / (1.f + expf(-x));
}
__device__ __forceinline__ float bfr(float x) {
    return __bfloat162float(__float2bfloat16(x));
}
__device__ __forceinline__ void mma16(float* d, const uint32_t* a, const uint32_t* b) {
    asm volatile(
        "mma.sync.aligned.m16n8k16.row.col.f32.bf16.bf16.f32 "
        "{%0,%1,%2,%3},{%4,%5,%6,%7},{%8,%9},{%0,%1,%2,%3};"
        : "+f"(d[0]), "+f"(d[1]), "+f"(d[2]), "+f"(d[3])
        : "r"(a[0]), "r"(a[1]), "r"(a[2]), "r"(a[3]), "r"(b[0]), "r"(b[1]));
}
__device__ __forceinline__ uint32_t pack_bf2(float a, float b) {
    __nv_bfloat162 t = __floats2bfloat162_rn(a, b);
    return *(uint32_t*)&t;
}
__device__ __forceinline__ uint32_t s2u(const void* p) {
    return (uint32_t)__cvta_generic_to_shared(p);
}
__device__ __forceinline__ void ldsm4(uint32_t* r, uint32_t a) {
    asm volatile("ldmatrix.sync.aligned.m8n8.x4.shared.b16 {%0,%1,%2,%3}, [%4];"
                 : "=r"(r[0]), "=r"(r[1]), "=r"(r[2]), "=r"(r[3]) : "r"(a));
}
__device__ __forceinline__ void ldsm2(uint32_t* r, uint32_t a) {
    asm volatile("ldmatrix.sync.aligned.m8n8.x2.shared.b16 {%0,%1}, [%2];"
                 : "=r"(r[0]), "=r"(r[1]) : "r"(a));
}

__device__ __forceinline__ void gbar(int idx) {
    __syncthreads();
    if (threadIdx.x == 0) {
        unsigned* cntp = &g_cnt[idx * 32];
        unsigned* genp = &g_gen[idx * 32];
        unsigned gen;
        asm volatile("ld.acquire.gpu.global.u32 %0, [%1];" : "=r"(gen) : "l"(genp));
        unsigned old;
        asm volatile("atom.release.gpu.global.add.u32 %0, [%1], %2;"
                     : "=r"(old) : "l"(cntp), "r"(1u));
        if (old == 15u) {
            asm volatile("st.relaxed.gpu.global.u32 [%0], %1;" :: "l"(cntp), "r"(0u));
            asm volatile("st.release.gpu.global.u32 [%0], %1;" :: "l"(genp), "r"(gen + 1u));
        } else {
            unsigned cur = gen;
            while (cur == gen) {
                __nanosleep(32);
                asm volatile("ld.acquire.gpu.global.u32 %0, [%1];" : "=r"(cur) : "l"(genp));
            }
        }
    }
    __syncthreads();
}

#define O_W  0
#define O_A  99840
#define O_AL 133120
#define O_Z  166400
#define O_SB 190976
#define O_SZ 199168
#define O_PB 211456
#define SMEM_BYTES 224256

__global__ void __launch_bounds__(NTHR, 1) mega(
    const float* __restrict__ x_states, const float* __restrict__ x_dts,
    const float* __restrict__ Wq, const float* __restrict__ bq,
    const float* __restrict__ Wk, const float* __restrict__ bk,
    const float* __restrict__ Wv, const float* __restrict__ bv,
    const float* __restrict__ W_gd, const float* __restrict__ b_gd,
    const float* __restrict__ W_tau, const float* __restrict__ b_tau,
    const float* __restrict__ gleak, const float* __restrict__ cm,
    const float* __restrict__ W_fc, const float* __restrict__ b_fc,
    float* __restrict__ out)
{
    extern __shared__ char smraw[];
    __shared__ float sleak[32], sbtau[32];
    uint32_t* Ws   = (uint32_t*)(smraw + O_W);
    uint32_t* AsHi = (uint32_t*)(smraw + O_A);
    uint32_t* AsLo = (uint32_t*)(smraw + O_AL);
    float (*zz)[96]    = (float(*)[96])(smraw + O_Z);
    float (*sbase)[64] = (float(*)[64])(smraw + O_SB);
    uint32_t uW  = s2u(smraw + O_W);
    uint32_t uA  = s2u(smraw + O_A);
    uint32_t uAL = s2u(smraw + O_AL);
    uint32_t uZ  = s2u(smraw + O_Z);
    uint32_t uPB = s2u(smraw + O_PB);

    int bid = blockIdx.x, tid = threadIdx.x;
    int lane = tid & 31, wid = tid >> 5;
    int gid = bid >> 4, hg = bid & 15;
    int m0 = gid * 32, h0 = hg * 32;

    // ===== prep =====
    if (tid < 32) {
        sleak[tid] = softplusf(cm[h0 + tid]) + softplusf(gleak[h0 + tid]);
        sbtau[tid] = b_tau[h0 + tid];
    }
    for (int idx = tid; idx < 96 * 256; idx += NTHR) {
        int n = idx >> 8, kq = idx & 255, k0 = kq * 2;
        float w0, w1;
        if (n < 32)      { w0 = W_gd[(64 + k0) * 1024 + h0 + n];       w1 = W_gd[(65 + k0) * 1024 + h0 + n]; }
        else if (n < 64) { w0 = W_gd[(64 + k0) * 1024 + 512 + h0 + n - 32]; w1 = W_gd[(65 + k0) * 1024 + 512 + h0 + n - 32]; }
        else             { w0 = W_tau[k0 * 512 + h0 + n - 64];         w1 = W_tau[(k0 + 1) * 512 + h0 + n - 64]; }
        float a = bfr(w0), b = bfr(w1);
        Ws[n * 260 + kq] = pack_bf2(a, b);
        g_WBLo[(hg * 96 + n) * 256 + kq] = pack_bf2(w0 - a, w1 - b);
    }
    for (int idx = tid; idx < 256 * 16; idx += NTHR) {
        int n = idx >> 4, kq = idx & 15;
        int k0 = h0 + 2 * kq, ncol = n & 127;
        const float* W = (n < 128) ? Wk : Wv;
        float w0 = W[k0 * 128 + ncol], w1 = W[(k0 + 1) * 128 + ncol];
        float a = bfr(w0), b = bfr(w1);
        g_WKV2Hi[bid * 4096 + idx] = pack_bf2(a, b);
        g_WKV2Lo[bid * 4096 + idx] = pack_bf2(w0 - a, w1 - b);
    }
    for (int idx = tid; idx < 64 * 96; idx += NTHR) {
        int n = idx / 96, kq = idx - n * 96, k0 = kq * 2;
        int row0 = (k0 < 64) ? k0 : (k0 + 512);
        int col = (n < 32) ? (h0 + n) : (512 + h0 + n - 32);
        float w0 = W_gd[row0 * 1024 + col], w1 = W_gd[(row0 + 1) * 1024 + col];
        float a = bfr(w0), b = bfr(w1);
        g_WBaseHi[(bid * 64 + n) * 96 + kq] = pack_bf2(a, b);
        g_WBaseLo[(bid * 64 + n) * 96 + kq] = pack_bf2(w0 - a, w1 - b);
    }
    for (int p = 0; p < 64; p++) {
        int bt = bid * 256 + p * 4 + (tid >> 7);
        int col = tid & 127;
        float q = bq[col];
        const float* xr = &x_states[bt * DD];
#pragma unroll 16
        for (int d = 0; d < DD; d++) q += __ldg(&xr[d]) * Wq[d * AA + col];
        g_Q[bt * AA + col] = q;
    }
    for (int idx = tid; idx < 32 * HH; idx += NTHR) g_h[m0 * HH + idx] = 0.f;
    {
        int mzr = tid >> 4, czc = tid & 15;
        g_hHi[(m0 + mzr) * 256 + hg * 16 + czc] = 0;
        g_hLo[(m0 + mzr) * 256 + hg * 16 + czc] = 0;
    }
    gbar(gid);

    float hreg[2] = {0.f, 0.f}, rk1[2], rk2[2], rk3[2], dd[2];
    float z0g[2], z0d[2], z0t[2];
    int kh = wid >> 3, wl = wid & 7;
    int wm = (wl >> 2) * 16, wn = (wl & 3) * 24;
    int qa = lane & 3;
    int aSel = (lane >> 4) << 2;
    int rowA_st = (wm + (lane & 15)) * 260 + aSel;
    // B x4 fragments: rows n, 4 k-quads across lane groups
    int bSel4 = ((lane >> 3) & 3) << 2;
    int rowB4_0 = (wn + 0 * 8 + (lane & 7)) * 260 + bSel4;
    int rowB4_1 = (wn + 1 * 8 + (lane & 7)) * 260 + bSel4;
    int rowB4_2 = (wn + 2 * 8 + (lane & 7)) * 260 + bSel4;
    long loBase = (long)(hg * 96 + wn + (lane >> 2)) * 256 + qa;
    int wbk2 = wid >> 3, wbm2 = (wid >> 2) & 1, wbn2 = wid & 3;
    int rowA_bs = (wbm2 * 16 + (lane & 15)) * 100 + aSel;
    int wnn = wid >> 1, wkm2 = wid & 1;
    int rowA_pk = (wkm2 * 16 + (lane & 15)) * 260 + aSel;

    for (int t = 0; t < TT; t++) {
        // ---- ATTN phase: sum KV partials (row t-1), stage A(h), attention ----
        {
#pragma unroll
            for (int i = 0; i < 4; i++) {
                int u4 = i * 512 + tid;
                int m = u4 >> 6, q4 = u4 & 63;
                *(uint4*)&AsHi[m * 260 + q4 * 4] = ((const uint4*)&g_hHi[(m0 + m) * 256])[q4];
                *(uint4*)&AsLo[m * 260 + q4 * 4] = ((const uint4*)&g_hLo[(m0 + m) * 256])[q4];
            }
            float* aq    = (float*)(smraw + O_SZ);
            float* asc   = aq + 256;
            float* actx  = asc + 256;
            float* ared  = actx + 512;
            float* spart = ared + 16;
            int hB = tid >> 8, lt = tid & 255;
            int b = bid * 2 + hB;
            if (t == 0) {
                if (lt < 128) g_ctx[b * AA + lt] = 0.f;
            } else {
                {
                    int n = lt;
                    int m = hg * 2 + hB;
                    const float* pp = &g_part[(gid * 16) * 8192 + m * 256 + n];
                    float s = 0.f;
#pragma unroll
                    for (int q = 0; q < 16; q++) s += pp[q * 8192];
                    if (n < 128) {
                        s += bk[n];
                        float os = __shfl_xor_sync(~0u, s, 1);
                        if (!(tid & 1))
                            g_KbT[(b * 64 + (n >> 1)) * TT + (t - 1)] = pack_bf2(s, os);
                    } else {
                        g_V[(b * TT + (t - 1)) * AA + (n - 128)] = s + bv[n - 128];
                    }
                }
                __syncthreads();
                if (lt < 128) aq[hB * 128 + lt] = g_Q[(b * TT + t) * AA + lt];
                __syncthreads();
                {
                    int tp = lt & 127, jh = lt >> 7;
                    float part = 0.f;
                    if (tp < t) {
                        const uint32_t* Kp = &g_KbT[(b * 64 + jh * 32) * TT + tp];
                        const float* qh = &aq[hB * 128 + jh * 64];
                        float dot = 0.f;
#pragma unroll 8
                        for (int j = 0; j < 32; j++) {
                            uint32_t kv = Kp[j * TT];
                            float2 f = __bfloat1622float2(*(__nv_bfloat162*)&kv);
                            dot += f.x * qh[2 * j] + f.y * qh[2 * j + 1];
                        }
                        part = dot;
                    }
                    spart[(hB * 2 + jh) * 128 + tp] = part;
                }
                __syncthreads();
                float s = -1e30f;
                if (lt < t)
                    s = (spart[hB * 256 + lt] + spart[hB * 256 + 128 + lt]) *
                        (1.f / 11.313708498984761f);
                float m = s;
#pragma unroll
                for (int o = 16; o > 0; o >>= 1) m = fmaxf(m, __shfl_xor_sync(~0u, m, o));
                if (lane == 0) ared[hB * 8 + (wid & 7)] = m;
                __syncthreads();
                m = ared[hB * 8];
#pragma unroll
                for (int i = 1; i < 8; i++) m = fmaxf(m, ared[hB * 8 + i]);
                float e = (lt < t) ? expf(s - m) : 0.f;
                float su = e;
#pragma unroll
                for (int o = 16; o > 0; o >>= 1) su += __shfl_xor_sync(~0u, su, o);
                __syncthreads();
                if (lane == 0) ared[hB * 8 + (wid & 7)] = su;
                __syncthreads();
                su = 0.f;
#pragma unroll
                for (int i = 0; i < 8; i++) su += ared[hB * 8 + i];
                if (lt < 128) asc[hB * 128 + lt] = (lt < t) ? (e / su) : 0.f;
                __syncthreads();
                {
                    int a = lt & 127, th = lt >> 7;
                    int tlim = (t + 7) & ~7;
                    float c = 0.f;
#pragma unroll 8
                    for (int sx = th; sx < tlim; sx += 2)
                        c += asc[hB * 128 + sx] * g_V[(b * TT + sx) * AA + a];
                    actx[(hB * 2 + th) * 128 + a] = c;
                }
                __syncthreads();
                if (lt < 128)
                    g_ctx[b * AA + lt] = actx[hB * 256 + lt] + actx[hB * 256 + 128 + lt];
            }
            gbar(gid);
        }

        // ---- 4 RK stages ----
        for (int stage = 0; stage < 4; stage++) {
            float acc[3][4];
#pragma unroll
            for (int s = 0; s < 3; s++)
#pragma unroll
                for (int i = 0; i < 4; i++) acc[s][i] = 0.f;

            if (stage == 0) {
                uint32_t* bAhi = (uint32_t*)(smraw + O_Z);
                uint32_t* bAlo = (uint32_t*)(smraw + O_PB);
#pragma unroll
                for (int i = 0; i < 6; i++) {
                    int idx = i * 512 + tid;
                    int m = idx / 96, kq = idx - m * 96;
                    int k0 = kq * 2;
                    float a0, a1;
                    if (kq < 32) {
                        const float* xr = &x_states[((m0 + m) * TT + t) * DD];
                        a0 = xr[k0]; a1 = xr[k0 + 1];
                    } else {
                        const float* cr = &g_ctx[(m0 + m) * AA];
                        a0 = cr[k0 - 64]; a1 = cr[k0 - 63];
                    }
                    float h0v = bfr(a0), h1v = bfr(a1);
                    bAhi[m * 100 + kq] = pack_bf2(h0v, h1v);
                    bAlo[m * 100 + kq] = pack_bf2(a0 - h0v, a1 - h1v);
                }
                __syncthreads();
                {
                    float accb[2][4];
#pragma unroll
                    for (int s = 0; s < 2; s++)
#pragma unroll
                        for (int i = 0; i < 4; i++) accb[s][i] = 0.f;
#pragma unroll
                    for (int ks = 0; ks < 6; ks++) {
                        int kq0 = wbk2 * 48 + ks * 8;
                        uint32_t ahi[4], alo[4];
                        ldsm4(ahi, uZ  + (rowA_bs + kq0) * 4);
                        ldsm4(alo, uPB + (rowA_bs + kq0) * 4);
#pragma unroll
                        for (int s = 0; s < 2; s++) {
                            int nrow = wbn2 * 16 + s * 8 + (lane >> 2);
                            long bix = (long)(bid * 64 + nrow) * 96 + kq0 + qa;
                            uint32_t bhi[2], blo[2];
                            bhi[0] = g_WBaseHi[bix]; bhi[1] = g_WBaseHi[bix + 4];
                            blo[0] = g_WBaseLo[bix]; blo[1] = g_WBaseLo[bix + 4];
                            mma16(accb[s], ahi, bhi);
                            mma16(accb[s], alo, bhi);
                            mma16(accb[s], ahi, blo);
                        }
                    }
                    __syncthreads();
                    float* pb = (float*)(smraw + O_Z);
#pragma unroll
                    for (int s = 0; s < 2; s++) {
                        int off = wbk2 * 2048 + (wbm2 * 16 + (lane >> 2)) * 64 +
                                  wbn2 * 16 + s * 8 + (lane & 3) * 2;
                        pb[off] = accb[s][0]; pb[off + 1] = accb[s][1];
                        pb[off + 512] = accb[s][2]; pb[off + 513] = accb[s][3];
                    }
                    __syncthreads();
#pragma unroll
                    for (int i = 0; i < 4; i++) {
                        int idx = i * 512 + tid;
                        int m = idx >> 6, n = idx & 63;
                        int col = (n < 32) ? (h0 + n) : (512 + h0 + n - 32);
                        sbase[m][n] = pb[m * 64 + n] + pb[2048 + m * 64 + n] + b_gd[col];
                    }
                }
                __syncthreads();
                // 3-term stage GEMM: (ahi+alo)@Whi + ahi@Wlo(LDG), B-hi via x4
#pragma unroll
                for (int it = 0; it < 8; it++) {
                    int kq0 = kh * 128 + it * 16;
                    uint32_t ahi0[4], ahi1[4], alo0[4], alo1[4];
                    ldsm4(ahi0, uA  + (rowA_st + kq0) * 4);
                    ldsm4(ahi1, uA  + (rowA_st + kq0 + 8) * 4);
                    ldsm4(alo0, uAL + (rowA_st + kq0) * 4);
                    ldsm4(alo1, uAL + (rowA_st + kq0 + 8) * 4);
                    uint32_t b4[4], bl[2];
#pragma unroll
                    for (int s = 0; s < 3; s++) {
                        int rb4 = (s == 0) ? rowB4_0 : ((s == 1) ? rowB4_1 : rowB4_2);
                        long lo = loBase + s * 2048 + kq0;
                        ldsm4(b4, uW + (rb4 + kq0) * 4);
                        bl[0] = g_WBLo[lo];     bl[1] = g_WBLo[lo + 4];
                        mma16(acc[s], ahi0, &b4[0]); mma16(acc[s], alo0, &b4[0]);
                        mma16(acc[s], ahi0, bl);
                        bl[0] = g_WBLo[lo + 8]; bl[1] = g_WBLo[lo + 12];
                        mma16(acc[s], ahi1, &b4[2]); mma16(acc[s], alo1, &b4[2]);
                        mma16(acc[s], ahi1, bl);
                    }
                }
                __syncthreads();
            } else {
                const uint32_t* Dg = (stage == 2) ? g_dB : g_dA;
#pragma unroll
                for (int i = 0; i < 4; i++) {
                    int idx = i * 512 + tid;
                    int m = idx >> 6, q4 = idx & 63;
                    *(uint4*)&AsHi[m * 260 + q4 * 4] = ((const uint4*)&Dg[(m0 + m) * 256])[q4];
                }
                __syncthreads();
#pragma unroll
                for (int it = 0; it < 8; it++) {
                    int kq0 = kh * 128 + it * 16;
                    uint32_t a0f[4], a1f[4], b4[4];
                    ldsm4(a0f, uA + (rowA_st + kq0) * 4);
                    ldsm4(a1f, uA + (rowA_st + kq0 + 8) * 4);
                    ldsm4(b4, uW + (rowB4_0 + kq0) * 4);
                    mma16(acc[0], a0f, &b4[0]); mma16(acc[0], a1f, &b4[2]);
                    ldsm4(b4, uW + (rowB4_1 + kq0) * 4);
                    mma16(acc[1], a0f, &b4[0]); mma16(acc[1], a1f, &b4[2]);
                    ldsm4(b4, uW + (rowB4_2 + kq0) * 4);
                    mma16(acc[2], a0f, &b4[0]); mma16(acc[2], a1f, &b4[2]);
                }
                __syncthreads();
            }

            {
                int rr = wm + (lane >> 2), cc = wn + (lane & 3) * 2;
#pragma unroll
                for (int s = 0; s < 3; s++) {
                    zz[kh * 32 + rr][cc + s * 8]         = acc[s][0];
                    zz[kh * 32 + rr][cc + s * 8 + 1]     = acc[s][1];
                    zz[kh * 32 + rr + 8][cc + s * 8]     = acc[s][2];
                    zz[kh * 32 + rr + 8][cc + s * 8 + 1] = acc[s][3];
                }
            }
            __syncthreads();

#pragma unroll
            for (int p = 0; p < 2; p++) {
                int idx = p * 512 + tid;
                int bl = idx >> 5, hh = idx & 31;
                int b = m0 + bl;
                float zg = zz[bl][hh]      + zz[32 + bl][hh];
                float zdn = zz[bl][32 + hh] + zz[32 + bl][32 + hh];
                float zt = zz[bl][64 + hh] + zz[32 + bl][64 + hh];
                if (stage == 0) {
                    z0g[p] = zg; z0d[p] = zdn; z0t[p] = zt;
                } else {
                    zg += z0g[p]; zdn += z0d[p]; zt += z0t[p];
                }
                float gate = zg + sbase[bl][hh];
                float dyn  = zdn + sbase[bl][32 + hh];
                float tau  = softplusf(zt + sbtau[hh]);
                float hsv  = (stage == 0) ? hreg[p] : (hreg[p] + dd[p]);
                float kd   = (sigmoidf(gate) * tanhf(dyn) - hsv) / (tau + sleak[hh] + 1e-6f);
                float dt   = x_dts[b * TT + t];
                if (stage == 3) {
                    hreg[p] += dt * (rk1[p] + 3.f * rk2[p] + 3.f * rk3[p] + kd) * 0.125f;
                    g_h[b * HH + h0 + hh] = hreg[p];
                    float hi = bfr(hreg[p]);
                    float lo = hreg[p] - hi;
                    float ohi = __shfl_xor_sync(~0u, hi, 1);
                    float olo = __shfl_xor_sync(~0u, lo, 1);
                    if (!(tid & 1)) {
                        uint32_t pkhi = pack_bf2(hi, ohi), pklo = pack_bf2(lo, olo);
                        g_hHi[b * 256 + ((h0 + hh) >> 1)] = pkhi;
                        g_hLo[b * 256 + ((h0 + hh) >> 1)] = pklo;
                        AsHi[bl * 260 + (hh >> 1)] = pkhi;
                        AsLo[bl * 260 + (hh >> 1)] = pklo;
                    }
                } else {
                    float dnew;
                    if (stage == 0)      { rk1[p] = kd; dnew = dt * kd * (1.f / 3.f); }
                    else if (stage == 1) { rk2[p] = kd; dnew = dt * (kd - rk1[p] * (1.f / 3.f)); }
                    else                 { rk3[p] = kd; dnew = dt * (rk1[p] - rk2[p] + kd); }
                    dd[p] = dnew;
                    float oth = __shfl_xor_sync(~0u, dnew, 1);
                    if (!(tid & 1)) {
                        uint32_t pk = pack_bf2(dnew, oth);
                        if (stage == 1) g_dB[b * 256 + ((h0 + hh) >> 1)] = pk;
                        else            g_dA[b * 256 + ((h0 + hh) >> 1)] = pk;
                    }
                }
            }

            // ---- stage3 tail: KV partial GEMM ----
            if (stage == 3) {
                __syncthreads();
                float ac[4][4];
#pragma unroll
                for (int s = 0; s < 4; s++)
#pragma unroll
                    for (int i = 0; i < 4; i++) ac[s][i] = 0.f;
#pragma unroll
                for (int kst = 0; kst < 2; kst++) {
                    uint32_t ahi[4], alo[4];
                    ldsm4(ahi, uA  + (rowA_pk + kst * 8) * 4);
                    ldsm4(alo, uAL + (rowA_pk + kst * 8) * 4);
#pragma unroll
                    for (int nt2 = 0; nt2 < 4; nt2++) {
                        int nrow = wnn * 32 + nt2 * 8 + (lane >> 2);
                        long wix = (long)(bid * 256 + nrow) * 16 + kst * 8 + qa;
                        uint32_t bh[2], bl2[2];
                        bh[0] = g_WKV2Hi[wix]; bh[1] = g_WKV2Hi[wix + 4];
                        bl2[0] = g_WKV2Lo[wix]; bl2[1] = g_WKV2Lo[wix + 4];
                        mma16(ac[nt2], ahi, bh);
                        mma16(ac[nt2], alo, bh);
                        mma16(ac[nt2], ahi, bl2);
                    }
                }
                float* gp = &g_part[bid * 8192];
#pragma unroll
                for (int nt2 = 0; nt2 < 4; nt2++) {
                    int m = wkm2 * 16 + (lane >> 2);
                    int n = wnn * 32 + nt2 * 8 + (lane & 3) * 2;
                    *(float2*)&gp[m * 256 + n]       = make_float2(ac[nt2][0], ac[nt2][1]);
                    *(float2*)&gp[(m + 8) * 256 + n] = make_float2(ac[nt2][2], ac[nt2][3]);
                }
            }
            gbar(gid);
        }
    }

    // ===== final projection =====
    {
        int b = bid * 2 + (tid >> 8);
        int lt = tid & 255;
        if (lt < OO) {
            float acc = b_fc[lt];
#pragma unroll 8
            for (int k = 0; k < HH; k++) acc += g_h[b * HH + k] * W_fc[k * OO + lt];
            out[b * OO + lt] = acc;
        }
    }
}

extern "C" void kernel_launch(void* const* d_in, const int* in_sizes, int n_in,
                              void* d_out, int out_size) {
    const float* x_states = (const float*)d_in[0];
    const float* x_dts    = (const float*)d_in[1];
    const float* Wq = (const float*)d_in[2];  const float* bq = (const float*)d_in[3];
    const float* Wk = (const float*)d_in[4];  const float* bk = (const float*)d_in[5];
    const float* Wv = (const float*)d_in[6];  const float* bv = (const float*)d_in[7];
    const float* W_gd = (const float*)d_in[8]; const float* b_gd = (const float*)d_in[9];
    const float* W_tau = (const float*)d_in[10]; const float* b_tau = (const float*)d_in[11];
    const float* gleak = (const float*)d_in[12]; const float* cm = (const float*)d_in[13];
    const float* W_fc = (const float*)d_in[14]; const float* b_fc = (const float*)d_in[15];
    float* out = (float*)d_out;

    cudaFuncSetAttribute(mega, cudaFuncAttributeMaxDynamicSharedMemorySize, SMEM_BYTES);
    mega<<<NBLK, NTHR, SMEM_BYTES>>>(x_states, x_dts, Wq, bq, Wk, bk, Wv, bv,
                                     W_gd, b_gd, W_tau, b_tau, gleak, cm,
                                     W_fc, b_fc, out);
}